// round 13
// baseline (speedup 1.0000x reference)
#include <cuda_runtime.h>
#include <cuda_fp16.h>
#include <math_constants.h>
#include <cstdint>
#include <cstddef>

#define BB   64
#define NN   1024
#define FF   5
#define WW   128
#define KNN  2
#define DD2  768
#define MTOT (BB*NN*KNN)   // 131072 edge rows

// ------------------------------------------------------------------ scratch
__device__ float d_y1[(size_t)BB*NN*WW];
__device__ float d_y2[(size_t)BB*NN*WW];
__device__ float d_y3[(size_t)BB*NN*WW];
__device__ uint32_t d_yh[2][(size_t)BB*NN*64];
__device__ uint32_t d_yl[2][(size_t)BB*NN*64];
__device__ float d_sq[BB*NN];
__device__ int   d_idx[MTOT];
__device__ float d_g [BB*DD2];
__device__ float d_hA[BB*DD2];
__device__ float d_hB[BB*DD2];
// pre-split conv weights
__device__ uint32_t d_w2h[128*64],  d_w2l[128*64];       // convAF W2: [n][kp]
__device__ uint32_t d_cwh[2*128*128], d_cwl[2*128*128];  // convB: [f][n][kp]

// ---------------------------------------------------------------- utilities
__device__ __forceinline__ bool lessdj(float d, int j, float D, int J) {
    return d < D || (d == D && j < J);
}
__device__ __forceinline__ void ins3u(unsigned long long k,
                                      unsigned long long& K1,
                                      unsigned long long& K2,
                                      unsigned long long& K3) {
    if (k < K3) {
        if (k < K2) {
            K3 = K2;
            if (k < K1) { K2 = K1; K1 = k; } else { K2 = k; }
        } else { K3 = k; }
    }
}
__device__ __forceinline__ void f16_split2(float x0, float x1,
                                           uint32_t& hw, uint32_t& lw) {
    __half h0 = __float2half_rn(x0);
    __half h1 = __float2half_rn(x1);
    float r0 = x0 - __half2float(h0);
    float r1 = x1 - __half2float(h1);
    __half l0 = __float2half_rn(r0);
    __half l1 = __float2half_rn(r1);
    hw = ((uint32_t)__half_as_ushort(h1) << 16) | (uint32_t)__half_as_ushort(h0);
    lw = ((uint32_t)__half_as_ushort(l1) << 16) | (uint32_t)__half_as_ushort(l0);
}
__device__ __forceinline__ void mma_f16(float c[4], uint32_t a0, uint32_t a1,
                                        uint32_t a2, uint32_t a3,
                                        uint32_t b0, uint32_t b1) {
    asm volatile(
        "mma.sync.aligned.m16n8k16.row.col.f32.f16.f16.f32 "
        "{%0,%1,%2,%3}, {%4,%5,%6,%7}, {%8,%9}, {%0,%1,%2,%3};"
        : "+f"(c[0]), "+f"(c[1]), "+f"(c[2]), "+f"(c[3])
        : "r"(a0), "r"(a1), "r"(a2), "r"(a3), "r"(b0), "r"(b1));
}
__device__ __forceinline__ void ldsm_x4(uint32_t r[4], uint32_t addr) {
    asm volatile("ldmatrix.sync.aligned.m8n8.x4.shared.b16 {%0,%1,%2,%3}, [%4];"
                 : "=r"(r[0]), "=r"(r[1]), "=r"(r[2]), "=r"(r[3]) : "r"(addr));
}
__device__ __forceinline__ uint32_t smem_u32(const void* p) {
    uint32_t a;
    asm("{ .reg .u64 t; cvta.to.shared.u64 t, %1; cvt.u32.u64 %0, t; }"
        : "=r"(a) : "l"(p));
    return a;
}
__device__ __forceinline__ void cp16(uint32_t dst, const void* src) {
    asm volatile("cp.async.cg.shared.global [%0], [%1], 16;"
                 :: "r"(dst), "l"(src) : "memory");
}
#define CP_COMMIT() asm volatile("cp.async.commit_group;" ::: "memory")
#define CP_WAIT0()  asm volatile("cp.async.wait_group 0;" ::: "memory")

// ---------------------------------------------------------- weight presplit
__global__ void __launch_bounds__(256) prep_conv_kernel(const float* __restrict__ W2,
                                                        const float* __restrict__ cw) {
    int idx = blockIdx.x*256 + threadIdx.x;
    if (idx < 128*64) {
        int kp = idx & 63, n = idx >> 6;
        uint32_t hw, lw;
        f16_split2(W2[(size_t)(2*kp)*128 + n], W2[(size_t)(2*kp+1)*128 + n], hw, lw);
        d_w2h[n*64 + kp] = hw; d_w2l[n*64 + kp] = lw;
    } else {
        int i2 = idx - 128*64;          // < 2*128*128
        int f = i2 >> 14, rem = i2 & 16383;
        int kp = rem & 127, n = rem >> 7;
        const float* wb = cw + (size_t)f*256*128;
        uint32_t hw, lw;
        f16_split2(wb[(size_t)(2*kp)*128 + n], wb[(size_t)(2*kp+1)*128 + n], hw, lw);
        d_cwh[f*16384 + n*128 + kp] = hw;
        d_cwl[f*16384 + n*128 + kp] = lw;
    }
}

// ------------------------------------------------------------ knn on x (D=5)
__global__ void __launch_bounds__(256) knn5_kernel(const float* __restrict__ x,
                                                   int* __restrict__ idx) {
    __shared__ float sx[NN*FF];
    __shared__ float ssq[NN];
    int b = blockIdx.y;
    const float* xb = x + (size_t)b*NN*FF;
    for (int v = threadIdx.x; v < NN*FF; v += 256) sx[v] = xb[v];
    __syncthreads();
    for (int v = threadIdx.x; v < NN; v += 256) {
        float s = 0.f;
        #pragma unroll
        for (int f = 0; f < FF; f++) { float t = sx[v*FF+f]; s += t*t; }
        ssq[v] = s;
    }
    __syncthreads();
    int i = blockIdx.x*256 + threadIdx.x;
    float xi[FF];
    #pragma unroll
    for (int f = 0; f < FF; f++) xi[f] = sx[i*FF+f];
    float sqi = ssq[i];
    float d1 = CUDART_INF_F, d2 = CUDART_INF_F;
    int j1 = 0, j2 = 0;
    for (int j = 0; j < NN; j++) {
        float dot = 0.f;
        #pragma unroll
        for (int f = 0; f < FF; f++) dot += xi[f]*sx[j*FF+f];
        float d = sqi + ssq[j] - 2.f*dot;
        if (d < d1)      { d2 = d1; j2 = j1; d1 = d; j1 = j; }
        else if (d < d2) { d2 = d;  j2 = j; }
    }
    int m = (b*NN + i)*KNN;
    idx[m] = j1; idx[m+1] = j2;
}

// --------------------------------------------------------------- sq norms
__global__ void __launch_bounds__(256) sqnorm_kernel(const float* __restrict__ y,
                                                     float* __restrict__ sq) {
    int w = threadIdx.x >> 5, lane = threadIdx.x & 31;
    int p = blockIdx.x*8 + w;
    const float* yp = y + (size_t)p*WW;
    float s = 0.f;
    #pragma unroll
    for (int c = 0; c < 4; c++) { float v = yp[lane + 32*c]; s += v*v; }
    #pragma unroll
    for (int o = 16; o; o >>= 1) s += __shfl_xor_sync(0xffffffffu, s, o);
    if (lane == 0) sq[p] = s;
}

// == knn on y (D=128): f16 3-term HMMA + cp.async ping-pong, u64 top-3/thread
#define OFF_AH 0
#define OFF_AL 34816
#define OFF_BP 69632
#define OFF_SQB 104448
#define KNNMMA_SMEM 104704

__global__ void __launch_bounds__(256, 2)
knn128_mma_kernel(const uint32_t* __restrict__ yh,
                  const uint32_t* __restrict__ yl,
                  const float* __restrict__ y,
                  const float* __restrict__ sq,
                  int* __restrict__ idx) {
    extern __shared__ char smem[];
    uint32_t* Ah = (uint32_t*)(smem + OFF_AH);
    uint32_t* Al = (uint32_t*)(smem + OFF_AL);
    unsigned long long* ck = (unsigned long long*)(smem + OFF_BP); // overlay: 128x24 keys
    uint32_t smb = smem_u32(smem);

    int tid = threadIdx.x, wid = tid >> 5, lane = tid & 31;
    int g = lane >> 2, tig = lane & 3;
    int band = wid & 3, half = wid >> 2;
    int b = blockIdx.y, i0 = blockIdx.x*128;
    const float* yb  = y + (size_t)b*NN*WW;
    const float* sqb = sq + b*NN;
    const uint4* yh4 = (const uint4*)(yh + (size_t)b*NN*64);
    const uint4* yl4 = (const uint4*)(yl + (size_t)b*NN*64);

    int mA = lane >> 3, rA = lane & 7;
    uint32_t aAddr = smb + OFF_AH +
        (uint32_t)(((band*32 + (mA & 1)*8 + rA)*68 + (mA >> 1)*4) * 4);
    uint32_t bOff =
        (uint32_t)(((half*16 + (mA >> 1)*8 + rA)*68 + (mA & 1)*4) * 4);

    for (int v = tid; v < 2048; v += 256) {
        int r = v >> 4, q = v & 15;
        *(uint4*)(Ah + r*68 + q*4) = yh4[(size_t)(i0+r)*16 + q];
        *(uint4*)(Al + r*68 + q*4) = yl4[(size_t)(i0+r)*16 + q];
    }

    auto issueB = [&](int ch) {
        int p = ch & 1;
        uint32_t base = smb + OFF_BP + (uint32_t)(p*17408);
        int jt = ch*32;
        #pragma unroll
        for (int w = 0; w < 4; w++) {
            int v = tid + w*256;
            int arr = v >> 9, r = (v >> 4) & 31, q = v & 15;
            uint32_t dst = base + (uint32_t)(arr*8704 + (r*68 + q*4)*4);
            const uint4* src = (arr ? yl4 : yh4) + (size_t)(jt + r)*16 + q;
            cp16(dst, src);
        }
        if (tid < 8)
            cp16(smb + OFF_SQB + (uint32_t)(p*128 + tid*16), sqb + jt + tid*4);
    };

    issueB(0);
    CP_COMMIT();

    // per-slot row constant: sqA + 4 (positivity shift; order-preserving)
    float sqA4[4];
    #pragma unroll
    for (int s = 0; s < 4; s++)
        sqA4[s] = sqb[i0 + band*32 + g + (s >> 1)*16 + (s & 1)*8] + 4.0f;

    unsigned long long K1[4], K2[4], K3[4];
    #pragma unroll
    for (int s = 0; s < 4; s++) {
        K1[s] = ~0ull; K2[s] = ~0ull; K3[s] = ~0ull;
    }

    for (int ch = 0; ch < 32; ch++) {
        CP_WAIT0();
        __syncthreads();
        if (ch + 1 < 32) { issueB(ch + 1); CP_COMMIT(); }

        uint32_t bb = smb + OFF_BP + (uint32_t)((ch & 1)*17408);
        int jt = ch*32;

        float acc[2][2][4];
        #pragma unroll
        for (int mt = 0; mt < 2; mt++)
            #pragma unroll
            for (int t = 0; t < 2; t++)
                #pragma unroll
                for (int q = 0; q < 4; q++) acc[mt][t][q] = 0.f;

        #pragma unroll
        for (int ks = 0; ks < 8; ks++) {
            uint32_t ah0[4], ah1[4], al0[4], al1[4], bh[4], bl[4];
            ldsm_x4(ah0, aAddr + ks*32);
            ldsm_x4(ah1, aAddr + 4352 + ks*32);
            ldsm_x4(al0, aAddr + 34816 + ks*32);
            ldsm_x4(al1, aAddr + 34816 + 4352 + ks*32);
            ldsm_x4(bh, bb + bOff + ks*32);
            ldsm_x4(bl, bb + 8704 + bOff + ks*32);
            #pragma unroll
            for (int t = 0; t < 2; t++) {
                uint32_t b0h = bh[2*t], b1h = bh[2*t+1];
                uint32_t b0l = bl[2*t], b1l = bl[2*t+1];
                mma_f16(acc[0][t], ah0[0], ah0[1], ah0[2], ah0[3], b0h, b1h);
                mma_f16(acc[0][t], ah0[0], ah0[1], ah0[2], ah0[3], b0l, b1l);
                mma_f16(acc[0][t], al0[0], al0[1], al0[2], al0[3], b0h, b1h);
                mma_f16(acc[1][t], ah1[0], ah1[1], ah1[2], ah1[3], b0h, b1h);
                mma_f16(acc[1][t], ah1[0], ah1[1], ah1[2], ah1[3], b0l, b1l);
                mma_f16(acc[1][t], al1[0], al1[1], al1[2], al1[3], b0h, b1h);
            }
        }

        const float* sqBs = (const float*)(smem + OFF_SQB + (ch & 1)*128);
        #pragma unroll
        for (int mt = 0; mt < 2; mt++)
            #pragma unroll
            for (int t = 0; t < 2; t++)
                #pragma unroll
                for (int q = 0; q < 4; q++) {
                    int jl = half*16 + t*8 + 2*tig + (q & 1);
                    int s = mt*2 + (q >> 1);
                    float dt = fmaf(-2.f, acc[mt][t][q], sqA4[s] + sqBs[jl]);
                    unsigned long long key =
                        ((unsigned long long)__float_as_uint(dt) << 32) |
                        (unsigned)(jt + jl);
                    ins3u(key, K1[s], K2[s], K3[s]);
                }
    }

    // NO cross-thread merge: 8 threads/row x top-3 -> 24 u64 candidates/row
    __syncthreads();   // mainloop fully done before overlaying B region
    {
        int thr = half*4 + tig;
        #pragma unroll
        for (int s = 0; s < 4; s++) {
            int row = band*32 + g + (s >> 1)*16 + (s & 1)*8;
            int base = row*24 + thr*3;
            ck[base + 0] = K1[s]; ck[base + 1] = K2[s]; ck[base + 2] = K3[s];
        }
    }
    __syncthreads();

    // final per-row: top-3 of 24 keys, fast-accept or exact fp32 recheck
    if (tid < 128) {
        int row = tid;
        unsigned long long k0 = ~0ull, k1 = ~0ull, k2 = ~0ull;
        #pragma unroll
        for (int q = 0; q < 24; q++) ins3u(ck[row*24 + q], k0, k1, k2);
        int o1 = (int)(unsigned)k0, o2 = (int)(unsigned)k1;
        float d1f = __uint_as_float((unsigned)(k0 >> 32));
        float d2f = __uint_as_float((unsigned)(k1 >> 32));
        float d3f = __uint_as_float((unsigned)(k2 >> 32));
        (void)d1f;
        if (d3f - d2f < 4e-3f) {
            float sqi = sqb[i0 + row];
            const float4* a4 = (const float4*)(yb + (size_t)(i0 + row)*WW);
            float e1 = CUDART_INF_F, e2 = CUDART_INF_F;
            int f1 = 0x7fffffff, f2 = 0x7fffffff;
            for (int q = 0; q < 24; q++) {
                int j = (int)(unsigned)ck[row*24 + q];
                const float4* b4 = (const float4*)(yb + (size_t)j*WW);
                float dot = 0.f;
                #pragma unroll
                for (int k = 0; k < 32; k++) {
                    float4 av = a4[k], bv = b4[k];
                    dot += av.x*bv.x + av.y*bv.y + av.z*bv.z + av.w*bv.w;
                }
                float d = sqi + sqb[j] - 2.f*dot;
                if (lessdj(d, j, e1, f1))      { e2 = e1; f2 = f1; e1 = d; f1 = j; }
                else if (lessdj(d, j, e2, f2)) { e2 = d; f2 = j; }
            }
            o1 = f1; o2 = f2;
        }
        int m = (b*NN + i0 + row)*KNN;
        idx[m] = o1; idx[m+1] = o2;
    }
}

// ====== conv1 FUSED (HMMA f16): edge(10)->relu h1(128) -> @W2 -> relu+max-k
#define CPAD 36
#define APAD 68
#define AF_HH 0
#define AF_HL 34816
#define AF_WH 69632
#define AF_WL 88064
#define AF_W1 106496
#define AF_B1 111616
#define AF_B2 112128
#define AF_IDX 112640
#define AF_SMEM 113152

__global__ void __launch_bounds__(256, 2)
convAF_mma_kernel(const float* __restrict__ x, const int* __restrict__ idxg,
                  const float* __restrict__ W1, const float* __restrict__ b1,
                  const float* __restrict__ b2,
                  float* __restrict__ yout,
                  uint32_t* __restrict__ yhout, uint32_t* __restrict__ ylout) {
    extern __shared__ char smem[];
    uint32_t* Hh  = (uint32_t*)(smem + AF_HH);
    uint32_t* Hl  = (uint32_t*)(smem + AF_HL);
    uint32_t* Wth = (uint32_t*)(smem + AF_WH);
    uint32_t* Wtl = (uint32_t*)(smem + AF_WL);
    float* w1s = (float*)(smem + AF_W1);
    float* b1s = (float*)(smem + AF_B1);
    float* b2s = (float*)(smem + AF_B2);
    int*   sidx = (int*)(smem + AF_IDX);

    int tid = threadIdx.x, lane = tid & 31, wid = tid >> 5;
    int g = lane >> 2, tig = lane & 3;
    int band = wid & 3, half = wid >> 2;
    int m0 = blockIdx.x*128;

    for (int v = tid; v < 10*128; v += 256) w1s[v] = W1[v];
    if (tid < 128) { b1s[tid] = b1[tid]; b2s[tid] = b2[tid]; sidx[tid] = idxg[m0 + tid]; }
    __syncthreads();

    {
        int r = tid >> 1;
        int m = m0 + r;
        int pg = m >> 1;
        int b  = pg >> 10;
        int j  = sidx[r];
        const float* xi = x + (size_t)pg*FF;
        const float* xj = x + ((size_t)b*NN + j)*FF;
        float e[10];
        #pragma unroll
        for (int f = 0; f < FF; f++) {
            float a = xi[f];
            e[f] = a; e[FF+f] = xj[f] - a;
        }
        int kpbase = (tid & 1)*32;
        #pragma unroll 2
        for (int q = 0; q < 32; q++) {
            int c0 = 2*(kpbase + q);
            float a0 = b1s[c0], a1 = b1s[c0+1];
            #pragma unroll
            for (int f = 0; f < 10; f++) {
                a0 += e[f]*w1s[f*128 + c0];
                a1 += e[f]*w1s[f*128 + c0 + 1];
            }
            a0 = fmaxf(a0, 0.f); a1 = fmaxf(a1, 0.f);
            uint32_t hw, lw; f16_split2(a0, a1, hw, lw);
            Hh[r*APAD + kpbase + q] = hw;
            Hl[r*APAD + kpbase + q] = lw;
        }
    }

    float acc[2][8][4];
    #pragma unroll
    for (int mt = 0; mt < 2; mt++)
        #pragma unroll
        for (int nt = 0; nt < 8; nt++)
            #pragma unroll
            for (int q = 0; q < 4; q++) acc[mt][nt][q] = 0.f;

    for (int chk = 0; chk < 2; chk++) {
        __syncthreads();
        for (int v = tid; v < 128*32; v += 256) {
            int n = v >> 5, kp = v & 31;
            Wth[n*CPAD + kp] = d_w2h[n*64 + chk*32 + kp];
            Wtl[n*CPAD + kp] = d_w2l[n*64 + chk*32 + kp];
        }
        __syncthreads();

        #pragma unroll
        for (int ks = 0; ks < 4; ks++) {
            int kbA = chk*32 + ks*8 + tig;
            int kbW = ks*8 + tig;
            uint32_t ah[2][4], al[2][4];
            #pragma unroll
            for (int mt = 0; mt < 2; mt++) {
                int r0 = (band*32 + mt*16 + g)*APAD;
                int r8 = r0 + 8*APAD;
                ah[mt][0] = Hh[r0 + kbA];     ah[mt][1] = Hh[r8 + kbA];
                ah[mt][2] = Hh[r0 + kbA + 4]; ah[mt][3] = Hh[r8 + kbA + 4];
                al[mt][0] = Hl[r0 + kbA];     al[mt][1] = Hl[r8 + kbA];
                al[mt][2] = Hl[r0 + kbA + 4]; al[mt][3] = Hl[r8 + kbA + 4];
            }
            #pragma unroll
            for (int nt = 0; nt < 8; nt++) {
                int nr = (half*64 + nt*8 + g)*CPAD;
                uint32_t bh0 = Wth[nr + kbW], bh1 = Wth[nr + kbW + 4];
                uint32_t bl0 = Wtl[nr + kbW], bl1 = Wtl[nr + kbW + 4];
                #pragma unroll
                for (int mt = 0; mt < 2; mt++) {
                    mma_f16(acc[mt][nt], ah[mt][0], ah[mt][1], ah[mt][2], ah[mt][3], bh0, bh1);
                    mma_f16(acc[mt][nt], ah[mt][0], ah[mt][1], ah[mt][2], ah[mt][3], bl0, bl1);
                    mma_f16(acc[mt][nt], al[mt][0], al[mt][1], al[mt][2], al[mt][3], bh0, bh1);
                }
            }
        }
    }

    bool writer = ((g & 1) == 0);
    #pragma unroll
    for (int mt = 0; mt < 2; mt++)
        #pragma unroll
        for (int nt = 0; nt < 8; nt++) {
            float c0 = acc[mt][nt][0], c1 = acc[mt][nt][1];
            float c2 = acc[mt][nt][2], c3 = acc[mt][nt][3];
            c0 = fmaxf(c0, __shfl_xor_sync(0xffffffffu, c0, 4));
            c1 = fmaxf(c1, __shfl_xor_sync(0xffffffffu, c1, 4));
            c2 = fmaxf(c2, __shfl_xor_sync(0xffffffffu, c2, 4));
            c3 = fmaxf(c3, __shfl_xor_sync(0xffffffffu, c3, 4));
            int col = half*64 + nt*8 + 2*tig;
            float bb0 = b2s[col], bb1 = b2s[col+1];
            if (writer) {
                int p0 = (m0 + band*32 + mt*16 + g) >> 1;
                float o00 = fmaxf(c0 + bb0, 0.f), o01 = fmaxf(c1 + bb1, 0.f);
                float o10 = fmaxf(c2 + bb0, 0.f), o11 = fmaxf(c3 + bb1, 0.f);
                *(float2*)(yout + (size_t)p0*128 + col) = make_float2(o00, o01);
                *(float2*)(yout + (size_t)(p0 + 4)*128 + col) = make_float2(o10, o11);
                uint32_t hw, lw;
                f16_split2(o00, o01, hw, lw);
                yhout[(size_t)p0*64 + (col >> 1)] = hw;
                ylout[(size_t)p0*64 + (col >> 1)] = lw;
                f16_split2(o10, o11, hw, lw);
                yhout[(size_t)(p0 + 4)*64 + (col >> 1)] = hw;
                ylout[(size_t)(p0 + 4)*64 + (col >> 1)] = lw;
            }
        }
}

// ======= conv2/3 (HMMA f16): gather edge(256) @ W(256x128) -> relu+max-k ===
#define CB_EH 0
#define CB_EL 18432
#define CB_WH 36864
#define CB_WL 55296
#define CB_BIAS 73728
#define CB_IDX  74240
#define CB_SMEM 74752

__global__ void __launch_bounds__(256, 2)
convB_mma_kernel(const float* __restrict__ yin,
                 const uint32_t* __restrict__ yhin, const uint32_t* __restrict__ ylin,
                 const int* __restrict__ idxg,
                 const uint32_t* __restrict__ cwh, const uint32_t* __restrict__ cwl,
                 const float* __restrict__ bias,
                 float* __restrict__ yout,
                 uint32_t* __restrict__ yhout, uint32_t* __restrict__ ylout) {
    extern __shared__ char smem[];
    uint32_t* Eh  = (uint32_t*)(smem + CB_EH);
    uint32_t* El  = (uint32_t*)(smem + CB_EL);
    uint32_t* Wth = (uint32_t*)(smem + CB_WH);
    uint32_t* Wtl = (uint32_t*)(smem + CB_WL);
    float* sbias = (float*)(smem + CB_BIAS);
    int*   sidx  = (int*)(smem + CB_IDX);

    int tid = threadIdx.x, lane = tid & 31, wid = tid >> 5;
    int g = lane >> 2, tig = lane & 3;
    int band = wid & 3, half = wid >> 2;
    int m0 = blockIdx.x*128;
    int bbase = ((m0 >> 1) >> 10) << 10;
    if (tid < 128) { sidx[tid] = idxg[m0 + tid]; sbias[tid] = bias[tid]; }

    float acc[2][8][4];
    #pragma unroll
    for (int mt = 0; mt < 2; mt++)
        #pragma unroll
        for (int nt = 0; nt < 8; nt++)
            #pragma unroll
            for (int q = 0; q < 4; q++) acc[mt][nt][q] = 0.f;

    for (int kc = 0; kc < 256; kc += 64) {
        __syncthreads();
        {
            bool ipart = kc < 128;
            if (ipart) {
                int kpb = kc >> 1;
                for (int v = tid; v < 128*32; v += 256) {
                    int r = v >> 5, kp = v & 31;
                    int ig = (m0 + r) >> 1;
                    Eh[r*CPAD + kp] = yhin[(size_t)ig*64 + kpb + kp];
                    El[r*CPAD + kp] = ylin[(size_t)ig*64 + kpb + kp];
                }
            } else {
                int fb = kc - 128;
                for (int v = tid; v < 128*32; v += 256) {
                    int r = v >> 5, kp = v & 31;
                    int ig = (m0 + r) >> 1;
                    int jg = bbase + sidx[r];
                    float2 xv = *(const float2*)(yin + (size_t)ig*128 + fb + 2*kp);
                    float2 bj = *(const float2*)(yin + (size_t)jg*128 + fb + 2*kp);
                    uint32_t hw, lw; f16_split2(bj.x - xv.x, bj.y - xv.y, hw, lw);
                    Eh[r*CPAD + kp] = hw; El[r*CPAD + kp] = lw;
                }
            }
        }
        {
            int kpb = kc >> 1;
            for (int v = tid; v < 128*32; v += 256) {
                int n = v >> 5, kp = v & 31;
                Wth[n*CPAD + kp] = cwh[n*128 + kpb + kp];
                Wtl[n*CPAD + kp] = cwl[n*128 + kpb + kp];
            }
        }
        __syncthreads();

        #pragma unroll
        for (int ks = 0; ks < 4; ks++) {
            int kb = ks*8 + tig;
            uint32_t ah[2][4], al[2][4];
            #pragma unroll
            for (int mt = 0; mt < 2; mt++) {
                int r0 = (band*32 + mt*16 + g)*CPAD;
                int r8 = r0 + 8*CPAD;
                ah[mt][0] = Eh[r0 + kb];     ah[mt][1] = Eh[r8 + kb];
                ah[mt][2] = Eh[r0 + kb + 4]; ah[mt][3] = Eh[r8 + kb + 4];
                al[mt][0] = El[r0 + kb];     al[mt][1] = El[r8 + kb];
                al[mt][2] = El[r0 + kb + 4]; al[mt][3] = El[r8 + kb + 4];
            }
            #pragma unroll
            for (int nt = 0; nt < 8; nt++) {
                int nr = (half*64 + nt*8 + g)*CPAD;
                uint32_t bh0 = Wth[nr + kb], bh1 = Wth[nr + kb + 4];
                uint32_t bl0 = Wtl[nr + kb], bl1 = Wtl[nr + kb + 4];
                #pragma unroll
                for (int mt = 0; mt < 2; mt++) {
                    mma_f16(acc[mt][nt], ah[mt][0], ah[mt][1], ah[mt][2], ah[mt][3], bh0, bh1);
                    mma_f16(acc[mt][nt], ah[mt][0], ah[mt][1], ah[mt][2], ah[mt][3], bl0, bl1);
                    mma_f16(acc[mt][nt], al[mt][0], al[mt][1], al[mt][2], al[mt][3], bh0, bh1);
                }
            }
        }
    }

    bool writer = ((g & 1) == 0);
    #pragma unroll
    for (int mt = 0; mt < 2; mt++)
        #pragma unroll
        for (int nt = 0; nt < 8; nt++) {
            float c0 = acc[mt][nt][0], c1 = acc[mt][nt][1];
            float c2 = acc[mt][nt][2], c3 = acc[mt][nt][3];
            c0 = fmaxf(c0, __shfl_xor_sync(0xffffffffu, c0, 4));
            c1 = fmaxf(c1, __shfl_xor_sync(0xffffffffu, c1, 4));
            c2 = fmaxf(c2, __shfl_xor_sync(0xffffffffu, c2, 4));
            c3 = fmaxf(c3, __shfl_xor_sync(0xffffffffu, c3, 4));
            int col = half*64 + nt*8 + 2*tig;
            float bb0 = sbias[col], bb1 = sbias[col+1];
            if (writer) {
                int p0 = (m0 + band*32 + mt*16 + g) >> 1;
                float o00 = fmaxf(c0 + bb0, 0.f), o01 = fmaxf(c1 + bb1, 0.f);
                float o10 = fmaxf(c2 + bb0, 0.f), o11 = fmaxf(c3 + bb1, 0.f);
                *(float2*)(yout + (size_t)p0*128 + col) = make_float2(o00, o01);
                *(float2*)(yout + (size_t)(p0 + 4)*128 + col) = make_float2(o10, o11);
                uint32_t hw, lw;
                f16_split2(o00, o01, hw, lw);
                yhout[(size_t)p0*64 + (col >> 1)] = hw;
                ylout[(size_t)p0*64 + (col >> 1)] = lw;
                f16_split2(o10, o11, hw, lw);
                yhout[(size_t)(p0 + 4)*64 + (col >> 1)] = hw;
                ylout[(size_t)(p0 + 4)*64 + (col >> 1)] = lw;
            }
        }
}

// ------------------------------------------------ mean/max pool over nodes
__global__ void __launch_bounds__(128) pool_kernel(const float* __restrict__ y1,
                                                   const float* __restrict__ y2,
                                                   const float* __restrict__ y3,
                                                   float* __restrict__ g) {
    int b = blockIdx.x, s = blockIdx.y, t = threadIdx.x;
    const float* src = (s == 0) ? y1 : ((s == 1) ? y2 : y3);
    const float* p = src + (size_t)b*NN*WW + t;
    float sum = 0.f, mx = -CUDART_INF_F;
    #pragma unroll 4
    for (int n = 0; n < NN; n++) {
        float v = p[(size_t)n*WW];
        sum += v; mx = fmaxf(mx, v);
    }
    int c = s*WW + t;
    g[b*DD2 + c]       = sum * (1.f/1024.f);
    g[b*DD2 + 384 + c] = mx;
}

// --------------------------------------------------- batchnorm (batch stats)
__global__ void __launch_bounds__(768) bn_kernel(const float* __restrict__ g,
                                                 const float* __restrict__ gam,
                                                 const float* __restrict__ bet,
                                                 float* __restrict__ h) {
    int c = threadIdx.x;
    float mu = 0.f;
    for (int b = 0; b < BB; b++) mu += g[b*DD2 + c];
    mu *= (1.f/64.f);
    float var = 0.f;
    for (int b = 0; b < BB; b++) { float d = g[b*DD2 + c] - mu; var += d*d; }
    var *= (1.f/64.f);
    float sc = rsqrtf(var + 1e-5f) * gam[c];
    float be = bet[c];
    for (int b = 0; b < BB; b++)
        h[b*DD2 + c] = (g[b*DD2 + c] - mu)*sc + be;
}

// --------------------------------------------- 768x768 linear + leaky relu
__global__ void __launch_bounds__(128) linear_kernel(const float* __restrict__ hin,
                                                     const float* __restrict__ Wt,
                                                     const float* __restrict__ bias,
                                                     float* __restrict__ hout) {
    __shared__ float sh[DD2];
    int b = blockIdx.x;
    for (int v = threadIdx.x; v < DD2; v += 128) sh[v] = hin[b*DD2 + v];
    __syncthreads();
    int o = blockIdx.y*128 + threadIdx.x;
    float acc = bias[o];
    #pragma unroll 8
    for (int k = 0; k < DD2; k++) acc += sh[k]*Wt[(size_t)k*DD2 + o];
    acc = (acc >= 0.f) ? acc : 0.01f*acc;
    hout[b*DD2 + o] = acc;
}

// ------------------------------------------------------------ output layer
__global__ void __launch_bounds__(256) out_kernel(const float* __restrict__ h,
                                                  const float* __restrict__ ow,
                                                  const float* __restrict__ ob,
                                                  float* __restrict__ out) {
    __shared__ float red[256];
    int b = blockIdx.x;
    float acc = 0.f;
    for (int k = threadIdx.x; k < DD2; k += 256) acc += h[b*DD2 + k]*ow[k];
    red[threadIdx.x] = acc;
    __syncthreads();
    for (int s = 128; s; s >>= 1) {
        if (threadIdx.x < s) red[threadIdx.x] += red[threadIdx.x + s];
        __syncthreads();
    }
    if (threadIdx.x == 0) out[b] = red[0] + ob[0];
}

// --------------------------------------------------------------------- host
extern "C" void kernel_launch(void* const* d_in, const int* in_sizes, int n_in,
                              void* d_out, int out_size) {
    (void)in_sizes; (void)n_in; (void)out_size;
    const float* x     = (const float*)d_in[0];
    const float* p1_w1 = (const float*)d_in[1];
    const float* p1_b1 = (const float*)d_in[2];
    const float* p1_w2 = (const float*)d_in[3];
    const float* p1_b2 = (const float*)d_in[4];
    const float* c_w   = (const float*)d_in[5];
    const float* c_b   = (const float*)d_in[6];
    const float* bng   = (const float*)d_in[7];
    const float* bnb   = (const float*)d_in[8];
    const float* lin_w = (const float*)d_in[9];
    const float* lin_b = (const float*)d_in[10];
    const float* out_w = (const float*)d_in[11];
    const float* out_b = (const float*)d_in[12];
    float* out = (float*)d_out;

    float *y1, *y2, *y3, *sq, *gg, *hA, *hB; int* idx;
    uint32_t *yh, *yl, *cwh, *cwl;
    cudaGetSymbolAddress((void**)&y1, d_y1);
    cudaGetSymbolAddress((void**)&y2, d_y2);
    cudaGetSymbolAddress((void**)&y3, d_y3);
    cudaGetSymbolAddress((void**)&yh, d_yh);
    cudaGetSymbolAddress((void**)&yl, d_yl);
    cudaGetSymbolAddress((void**)&sq, d_sq);
    cudaGetSymbolAddress((void**)&gg, d_g);
    cudaGetSymbolAddress((void**)&hA, d_hA);
    cudaGetSymbolAddress((void**)&hB, d_hB);
    cudaGetSymbolAddress((void**)&idx, d_idx);
    cudaGetSymbolAddress((void**)&cwh, d_cwh);
    cudaGetSymbolAddress((void**)&cwl, d_cwl);

    const size_t YSP = (size_t)BB*NN*64;   // per-buffer size of yh/yl

    cudaFuncSetAttribute((const void*)knn128_mma_kernel,
                         cudaFuncAttributeMaxDynamicSharedMemorySize, KNNMMA_SMEM);
    cudaFuncSetAttribute((const void*)convAF_mma_kernel,
                         cudaFuncAttributeMaxDynamicSharedMemorySize, AF_SMEM);
    cudaFuncSetAttribute((const void*)convB_mma_kernel,
                         cudaFuncAttributeMaxDynamicSharedMemorySize, CB_SMEM);

    prep_conv_kernel<<<(128*64 + 2*128*128)/256, 256>>>(p1_w2, c_w);

    knn5_kernel  <<<dim3(4, BB), 256>>>(x, idx);
    convAF_mma_kernel<<<MTOT/128, 256, AF_SMEM>>>(x, idx, p1_w1, p1_b1, p1_b2,
                                                  y1, yh, yl);

    sqnorm_kernel<<<(BB*NN)/8, 256>>>(y1, sq);
    knn128_mma_kernel<<<dim3(NN/128, BB), 256, KNNMMA_SMEM>>>(yh, yl, y1, sq, idx);
    convB_mma_kernel<<<MTOT/128, 256, CB_SMEM>>>(y1, yh, yl, idx, cwh, cwl, c_b,
                                                 y2, yh + YSP, yl + YSP);

    sqnorm_kernel<<<(BB*NN)/8, 256>>>(y2, sq);
    knn128_mma_kernel<<<dim3(NN/128, BB), 256, KNNMMA_SMEM>>>(yh + YSP, yl + YSP,
                                                              y2, sq, idx);
    convB_mma_kernel<<<MTOT/128, 256, CB_SMEM>>>(y2, yh + YSP, yl + YSP, idx,
                                                 cwh + 16384, cwl + 16384,
                                                 c_b + 128, y3, yh, yl);

    pool_kernel<<<dim3(BB, 3), 128>>>(y1, y2, y3, gg);
    bn_kernel  <<<1, 768>>>(gg, bng, bnb, hA);

    const float* lin_in = hA; float* lin_out = hB;
    for (int l = 0; l < 5; l++) {
        linear_kernel<<<dim3(BB, DD2/128), 128>>>(lin_in,
                                                  lin_w + (size_t)l*DD2*DD2,
                                                  lin_b + l*DD2, lin_out);
        const float* t = lin_in; lin_in = lin_out; lin_out = (float*)t;
    }
    out_kernel<<<BB, 256>>>(lin_in, out_w, out_b, out);
}

// round 14
// speedup vs baseline: 1.0321x; 1.0321x over previous
#include <cuda_runtime.h>
#include <cuda_fp16.h>
#include <math_constants.h>
#include <cstdint>
#include <cstddef>

#define BB   64
#define NN   1024
#define FF   5
#define WW   128
#define KNN  2
#define DD2  768
#define MTOT (BB*NN*KNN)   // 131072 edge rows

// ------------------------------------------------------------------ scratch
__device__ float d_y1[(size_t)BB*NN*WW];
__device__ float d_y2[(size_t)BB*NN*WW];
__device__ float d_y3[(size_t)BB*NN*WW];
__device__ uint32_t d_yh[2][(size_t)BB*NN*64];
__device__ uint32_t d_yl[2][(size_t)BB*NN*64];
__device__ float d_sq[BB*NN];
__device__ int   d_idx[MTOT];
__device__ float d_g [BB*DD2];
__device__ float d_hA[BB*DD2];
__device__ float d_hB[BB*DD2];
// pre-split conv weights
__device__ uint32_t d_w2h[128*64],  d_w2l[128*64];       // convAF W2: [n][kp]
__device__ uint32_t d_cwh[2*128*128], d_cwl[2*128*128];  // convB: [f][n][kp]

// ---------------------------------------------------------------- utilities
__device__ __forceinline__ bool lessdj(float d, int j, float D, int J) {
    return d < D || (d == D && j < J);
}
__device__ __forceinline__ void ins3(float nd, int nj,
                                     float& D1, int& J1, float& D2, int& J2,
                                     float& D3, int& J3) {
    if (lessdj(nd, nj, D3, J3)) {
        if (lessdj(nd, nj, D2, J2)) {
            D3 = D2; J3 = J2;
            if (lessdj(nd, nj, D1, J1)) { D2 = D1; J2 = J1; D1 = nd; J1 = nj; }
            else { D2 = nd; J2 = nj; }
        } else { D3 = nd; J3 = nj; }
    }
}
__device__ __forceinline__ void f16_split2(float x0, float x1,
                                           uint32_t& hw, uint32_t& lw) {
    __half h0 = __float2half_rn(x0);
    __half h1 = __float2half_rn(x1);
    float r0 = x0 - __half2float(h0);
    float r1 = x1 - __half2float(h1);
    __half l0 = __float2half_rn(r0);
    __half l1 = __float2half_rn(r1);
    hw = ((uint32_t)__half_as_ushort(h1) << 16) | (uint32_t)__half_as_ushort(h0);
    lw = ((uint32_t)__half_as_ushort(l1) << 16) | (uint32_t)__half_as_ushort(l0);
}
__device__ __forceinline__ void mma_f16(float c[4], uint32_t a0, uint32_t a1,
                                        uint32_t a2, uint32_t a3,
                                        uint32_t b0, uint32_t b1) {
    asm volatile(
        "mma.sync.aligned.m16n8k16.row.col.f32.f16.f16.f32 "
        "{%0,%1,%2,%3}, {%4,%5,%6,%7}, {%8,%9}, {%0,%1,%2,%3};"
        : "+f"(c[0]), "+f"(c[1]), "+f"(c[2]), "+f"(c[3])
        : "r"(a0), "r"(a1), "r"(a2), "r"(a3), "r"(b0), "r"(b1));
}
__device__ __forceinline__ void ldsm_x4(uint32_t r[4], uint32_t addr) {
    asm volatile("ldmatrix.sync.aligned.m8n8.x4.shared.b16 {%0,%1,%2,%3}, [%4];"
                 : "=r"(r[0]), "=r"(r[1]), "=r"(r[2]), "=r"(r[3]) : "r"(addr));
}
__device__ __forceinline__ uint32_t smem_u32(const void* p) {
    uint32_t a;
    asm("{ .reg .u64 t; cvta.to.shared.u64 t, %1; cvt.u32.u64 %0, t; }"
        : "=r"(a) : "l"(p));
    return a;
}
__device__ __forceinline__ void cp16(uint32_t dst, const void* src) {
    asm volatile("cp.async.cg.shared.global [%0], [%1], 16;"
                 :: "r"(dst), "l"(src) : "memory");
}
#define CP_COMMIT() asm volatile("cp.async.commit_group;" ::: "memory")
#define CP_WAIT0()  asm volatile("cp.async.wait_group 0;" ::: "memory")

// ---------------------------------------------------------- weight presplit
__global__ void __launch_bounds__(256) prep_conv_kernel(const float* __restrict__ W2,
                                                        const float* __restrict__ cw) {
    int idx = blockIdx.x*256 + threadIdx.x;
    if (idx < 128*64) {
        int kp = idx & 63, n = idx >> 6;
        uint32_t hw, lw;
        f16_split2(W2[(size_t)(2*kp)*128 + n], W2[(size_t)(2*kp+1)*128 + n], hw, lw);
        d_w2h[n*64 + kp] = hw; d_w2l[n*64 + kp] = lw;
    } else {
        int i2 = idx - 128*64;          // < 2*128*128
        int f = i2 >> 14, rem = i2 & 16383;
        int kp = rem & 127, n = rem >> 7;
        const float* wb = cw + (size_t)f*256*128;
        uint32_t hw, lw;
        f16_split2(wb[(size_t)(2*kp)*128 + n], wb[(size_t)(2*kp+1)*128 + n], hw, lw);
        d_cwh[f*16384 + n*128 + kp] = hw;
        d_cwl[f*16384 + n*128 + kp] = lw;
    }
}

// ------------------------------------------------------------ knn on x (D=5)
__global__ void __launch_bounds__(256) knn5_kernel(const float* __restrict__ x,
                                                   int* __restrict__ idx) {
    __shared__ float sx[NN*FF];
    __shared__ float ssq[NN];
    int b = blockIdx.y;
    const float* xb = x + (size_t)b*NN*FF;
    for (int v = threadIdx.x; v < NN*FF; v += 256) sx[v] = xb[v];
    __syncthreads();
    for (int v = threadIdx.x; v < NN; v += 256) {
        float s = 0.f;
        #pragma unroll
        for (int f = 0; f < FF; f++) { float t = sx[v*FF+f]; s += t*t; }
        ssq[v] = s;
    }
    __syncthreads();
    int i = blockIdx.x*256 + threadIdx.x;
    float xi[FF];
    #pragma unroll
    for (int f = 0; f < FF; f++) xi[f] = sx[i*FF+f];
    float sqi = ssq[i];
    float d1 = CUDART_INF_F, d2 = CUDART_INF_F;
    int j1 = 0, j2 = 0;
    for (int j = 0; j < NN; j++) {
        float dot = 0.f;
        #pragma unroll
        for (int f = 0; f < FF; f++) dot += xi[f]*sx[j*FF+f];
        float d = sqi + ssq[j] - 2.f*dot;
        if (d < d1)      { d2 = d1; j2 = j1; d1 = d; j1 = j; }
        else if (d < d2) { d2 = d;  j2 = j; }
    }
    int m = (b*NN + i)*KNN;
    idx[m] = j1; idx[m+1] = j2;
}

// --------------------------------------------------------------- sq norms
__global__ void __launch_bounds__(256) sqnorm_kernel(const float* __restrict__ y,
                                                     float* __restrict__ sq) {
    int w = threadIdx.x >> 5, lane = threadIdx.x & 31;
    int p = blockIdx.x*8 + w;
    const float* yp = y + (size_t)p*WW;
    float s = 0.f;
    #pragma unroll
    for (int c = 0; c < 4; c++) { float v = yp[lane + 32*c]; s += v*v; }
    #pragma unroll
    for (int o = 16; o; o >>= 1) s += __shfl_xor_sync(0xffffffffu, s, o);
    if (lane == 0) sq[p] = s;
}

// == knn on y (D=128): f16 3-term HMMA + cp.async ping-pong,
//    guarded top-3/thread (rare insert), merge-free 24-candidate epilogue
#define OFF_AH 0
#define OFF_AL 34816
#define OFF_BP 69632
#define OFF_SQB 104448
#define KNNMMA_SMEM 104704

__global__ void __launch_bounds__(256, 2)
knn128_mma_kernel(const uint32_t* __restrict__ yh,
                  const uint32_t* __restrict__ yl,
                  const float* __restrict__ y,
                  const float* __restrict__ sq,
                  int* __restrict__ idx) {
    extern __shared__ char smem[];
    uint32_t* Ah = (uint32_t*)(smem + OFF_AH);
    uint32_t* Al = (uint32_t*)(smem + OFF_AL);
    float* cf    = (float*)(smem + OFF_BP);          // overlay: 128x24 dists
    int*   ci    = (int*)(smem + OFF_BP + 12288);    // overlay: 128x24 idx
    uint32_t smb = smem_u32(smem);

    int tid = threadIdx.x, wid = tid >> 5, lane = tid & 31;
    int g = lane >> 2, tig = lane & 3;
    int band = wid & 3, half = wid >> 2;
    int b = blockIdx.y, i0 = blockIdx.x*128;
    const float* yb  = y + (size_t)b*NN*WW;
    const float* sqb = sq + b*NN;
    const uint4* yh4 = (const uint4*)(yh + (size_t)b*NN*64);
    const uint4* yl4 = (const uint4*)(yl + (size_t)b*NN*64);

    int mA = lane >> 3, rA = lane & 7;
    uint32_t aAddr = smb + OFF_AH +
        (uint32_t)(((band*32 + (mA & 1)*8 + rA)*68 + (mA >> 1)*4) * 4);
    uint32_t bOff =
        (uint32_t)(((half*16 + (mA >> 1)*8 + rA)*68 + (mA & 1)*4) * 4);

    for (int v = tid; v < 2048; v += 256) {
        int r = v >> 4, q = v & 15;
        *(uint4*)(Ah + r*68 + q*4) = yh4[(size_t)(i0+r)*16 + q];
        *(uint4*)(Al + r*68 + q*4) = yl4[(size_t)(i0+r)*16 + q];
    }

    auto issueB = [&](int ch) {
        int p = ch & 1;
        uint32_t base = smb + OFF_BP + (uint32_t)(p*17408);
        int jt = ch*32;
        #pragma unroll
        for (int w = 0; w < 4; w++) {
            int v = tid + w*256;
            int arr = v >> 9, r = (v >> 4) & 31, q = v & 15;
            uint32_t dst = base + (uint32_t)(arr*8704 + (r*68 + q*4)*4);
            const uint4* src = (arr ? yl4 : yh4) + (size_t)(jt + r)*16 + q;
            cp16(dst, src);
        }
        if (tid < 8)
            cp16(smb + OFF_SQB + (uint32_t)(p*128 + tid*16), sqb + jt + tid*4);
    };

    issueB(0);
    CP_COMMIT();

    // per-slot row sq norm (slot s -> row band*32 + g + (s>>1)*16 + (s&1)*8)
    float sqAr[4];
    #pragma unroll
    for (int s = 0; s < 4; s++)
        sqAr[s] = sqb[i0 + band*32 + g + (s >> 1)*16 + (s & 1)*8];

    float D1[4], D2[4], D3[4]; int J1[4], J2[4], J3[4];
    #pragma unroll
    for (int s = 0; s < 4; s++) {
        D1[s] = CUDART_INF_F; D2[s] = CUDART_INF_F; D3[s] = CUDART_INF_F;
        J1[s] = 0x7fffffff;   J2[s] = 0x7fffffff;   J3[s] = 0x7fffffff;
    }

    for (int ch = 0; ch < 32; ch++) {
        CP_WAIT0();
        __syncthreads();
        if (ch + 1 < 32) { issueB(ch + 1); CP_COMMIT(); }

        uint32_t bb = smb + OFF_BP + (uint32_t)((ch & 1)*17408);
        int jt = ch*32;

        float acc[2][2][4];
        #pragma unroll
        for (int mt = 0; mt < 2; mt++)
            #pragma unroll
            for (int t = 0; t < 2; t++)
                #pragma unroll
                for (int q = 0; q < 4; q++) acc[mt][t][q] = 0.f;

        #pragma unroll
        for (int ks = 0; ks < 8; ks++) {
            uint32_t ah0[4], ah1[4], al0[4], al1[4], bh[4], bl[4];
            ldsm_x4(ah0, aAddr + ks*32);
            ldsm_x4(ah1, aAddr + 4352 + ks*32);
            ldsm_x4(al0, aAddr + 34816 + ks*32);
            ldsm_x4(al1, aAddr + 34816 + 4352 + ks*32);
            ldsm_x4(bh, bb + bOff + ks*32);
            ldsm_x4(bl, bb + 8704 + bOff + ks*32);
            #pragma unroll
            for (int t = 0; t < 2; t++) {
                uint32_t b0h = bh[2*t], b1h = bh[2*t+1];
                uint32_t b0l = bl[2*t], b1l = bl[2*t+1];
                mma_f16(acc[0][t], ah0[0], ah0[1], ah0[2], ah0[3], b0h, b1h);
                mma_f16(acc[0][t], ah0[0], ah0[1], ah0[2], ah0[3], b0l, b1l);
                mma_f16(acc[0][t], al0[0], al0[1], al0[2], al0[3], b0h, b1h);
                mma_f16(acc[1][t], ah1[0], ah1[1], ah1[2], ah1[3], b0h, b1h);
                mma_f16(acc[1][t], ah1[0], ah1[1], ah1[2], ah1[3], b0l, b1l);
                mma_f16(acc[1][t], al1[0], al1[1], al1[2], al1[3], b0h, b1h);
            }
        }

        // guarded selection: per slot, 4 candidates; rare precise insert
        const float* sqBs = (const float*)(smem + OFF_SQB + (ch & 1)*128);
        #pragma unroll
        for (int s = 0; s < 4; s++) {
            int mt = s >> 1, q0 = (s & 1)*2;
            int jb = jt + half*16 + 2*tig;
            float v0 = fmaf(-2.f, acc[mt][0][q0],   sqAr[s] + sqBs[jb - jt]);
            float v1 = fmaf(-2.f, acc[mt][0][q0+1], sqAr[s] + sqBs[jb - jt + 1]);
            float v2 = fmaf(-2.f, acc[mt][1][q0],   sqAr[s] + sqBs[jb - jt + 8]);
            float v3 = fmaf(-2.f, acc[mt][1][q0+1], sqAr[s] + sqBs[jb - jt + 9]);
            float mn = fminf(fminf(v0, v1), fminf(v2, v3));
            if (mn <= D3[s]) {
                ins3(v0, jb,     D1[s], J1[s], D2[s], J2[s], D3[s], J3[s]);
                ins3(v1, jb + 1, D1[s], J1[s], D2[s], J2[s], D3[s], J3[s]);
                ins3(v2, jb + 8, D1[s], J1[s], D2[s], J2[s], D3[s], J3[s]);
                ins3(v3, jb + 9, D1[s], J1[s], D2[s], J2[s], D3[s], J3[s]);
            }
        }
    }

    // NO cross-thread merge: 8 threads/row x top-3 -> 24 candidates/row
    __syncthreads();   // mainloop fully done before overlaying B region
    {
        int thr = half*4 + tig;
        #pragma unroll
        for (int s = 0; s < 4; s++) {
            int row = band*32 + g + (s >> 1)*16 + (s & 1)*8;
            int base = row*24 + thr*3;
            cf[base + 0] = D1[s]; ci[base + 0] = J1[s];
            cf[base + 1] = D2[s]; ci[base + 1] = J2[s];
            cf[base + 2] = D3[s]; ci[base + 2] = J3[s];
        }
    }
    __syncthreads();

    // final per-row: top-3 of 24 candidates, fast-accept or exact recheck
    if (tid < 128) {
        int row = tid;
        float m0 = CUDART_INF_F, m1 = CUDART_INF_F, m2 = CUDART_INF_F;
        int n0 = 0x7fffffff, n1 = 0x7fffffff, n2 = 0x7fffffff;
        #pragma unroll
        for (int q = 0; q < 24; q++) {
            float d = cf[row*24 + q]; int j = ci[row*24 + q];
            ins3(d, j, m0, n0, m1, n1, m2, n2);
        }
        int o1 = n0, o2 = n1;
        if (m2 - m1 < 4e-3f) {
            float sqi = sqb[i0 + row];
            const float4* a4 = (const float4*)(yb + (size_t)(i0 + row)*WW);
            float e1 = CUDART_INF_F, e2 = CUDART_INF_F;
            int f1 = 0x7fffffff, f2 = 0x7fffffff;
            for (int q = 0; q < 24; q++) {
                int j = ci[row*24 + q];
                if (j == 0x7fffffff) continue;
                const float4* b4 = (const float4*)(yb + (size_t)j*WW);
                float dot = 0.f;
                #pragma unroll
                for (int k = 0; k < 32; k++) {
                    float4 av = a4[k], bv = b4[k];
                    dot += av.x*bv.x + av.y*bv.y + av.z*bv.z + av.w*bv.w;
                }
                float d = sqi + sqb[j] - 2.f*dot;
                if (lessdj(d, j, e1, f1))      { e2 = e1; f2 = f1; e1 = d; f1 = j; }
                else if (lessdj(d, j, e2, f2)) { e2 = d; f2 = j; }
            }
            o1 = f1; o2 = f2;
        }
        int m = (b*NN + i0 + row)*KNN;
        idx[m] = o1; idx[m+1] = o2;
    }
}

// ====== conv1 FUSED (HMMA f16): edge(10)->relu h1(128) -> @W2 -> relu+max-k
#define CPAD 36
#define APAD 68
#define AF_HH 0
#define AF_HL 34816
#define AF_WH 69632
#define AF_WL 88064
#define AF_W1 106496
#define AF_B1 111616
#define AF_B2 112128
#define AF_IDX 112640
#define AF_SMEM 113152

__global__ void __launch_bounds__(256, 2)
convAF_mma_kernel(const float* __restrict__ x, const int* __restrict__ idxg,
                  const float* __restrict__ W1, const float* __restrict__ b1,
                  const float* __restrict__ b2,
                  float* __restrict__ yout,
                  uint32_t* __restrict__ yhout, uint32_t* __restrict__ ylout) {
    extern __shared__ char smem[];
    uint32_t* Hh  = (uint32_t*)(smem + AF_HH);
    uint32_t* Hl  = (uint32_t*)(smem + AF_HL);
    uint32_t* Wth = (uint32_t*)(smem + AF_WH);
    uint32_t* Wtl = (uint32_t*)(smem + AF_WL);
    float* w1s = (float*)(smem + AF_W1);
    float* b1s = (float*)(smem + AF_B1);
    float* b2s = (float*)(smem + AF_B2);
    int*   sidx = (int*)(smem + AF_IDX);

    int tid = threadIdx.x, lane = tid & 31, wid = tid >> 5;
    int g = lane >> 2, tig = lane & 3;
    int band = wid & 3, half = wid >> 2;
    int m0 = blockIdx.x*128;

    for (int v = tid; v < 10*128; v += 256) w1s[v] = W1[v];
    if (tid < 128) { b1s[tid] = b1[tid]; b2s[tid] = b2[tid]; sidx[tid] = idxg[m0 + tid]; }
    __syncthreads();

    {
        int r = tid >> 1;
        int m = m0 + r;
        int pg = m >> 1;
        int b  = pg >> 10;
        int j  = sidx[r];
        const float* xi = x + (size_t)pg*FF;
        const float* xj = x + ((size_t)b*NN + j)*FF;
        float e[10];
        #pragma unroll
        for (int f = 0; f < FF; f++) {
            float a = xi[f];
            e[f] = a; e[FF+f] = xj[f] - a;
        }
        int kpbase = (tid & 1)*32;
        #pragma unroll 2
        for (int q = 0; q < 32; q++) {
            int c0 = 2*(kpbase + q);
            float a0 = b1s[c0], a1 = b1s[c0+1];
            #pragma unroll
            for (int f = 0; f < 10; f++) {
                a0 += e[f]*w1s[f*128 + c0];
                a1 += e[f]*w1s[f*128 + c0 + 1];
            }
            a0 = fmaxf(a0, 0.f); a1 = fmaxf(a1, 0.f);
            uint32_t hw, lw; f16_split2(a0, a1, hw, lw);
            Hh[r*APAD + kpbase + q] = hw;
            Hl[r*APAD + kpbase + q] = lw;
        }
    }

    float acc[2][8][4];
    #pragma unroll
    for (int mt = 0; mt < 2; mt++)
        #pragma unroll
        for (int nt = 0; nt < 8; nt++)
            #pragma unroll
            for (int q = 0; q < 4; q++) acc[mt][nt][q] = 0.f;

    for (int chk = 0; chk < 2; chk++) {
        __syncthreads();
        for (int v = tid; v < 128*32; v += 256) {
            int n = v >> 5, kp = v & 31;
            Wth[n*CPAD + kp] = d_w2h[n*64 + chk*32 + kp];
            Wtl[n*CPAD + kp] = d_w2l[n*64 + chk*32 + kp];
        }
        __syncthreads();

        #pragma unroll
        for (int ks = 0; ks < 4; ks++) {
            int kbA = chk*32 + ks*8 + tig;
            int kbW = ks*8 + tig;
            uint32_t ah[2][4], al[2][4];
            #pragma unroll
            for (int mt = 0; mt < 2; mt++) {
                int r0 = (band*32 + mt*16 + g)*APAD;
                int r8 = r0 + 8*APAD;
                ah[mt][0] = Hh[r0 + kbA];     ah[mt][1] = Hh[r8 + kbA];
                ah[mt][2] = Hh[r0 + kbA + 4]; ah[mt][3] = Hh[r8 + kbA + 4];
                al[mt][0] = Hl[r0 + kbA];     al[mt][1] = Hl[r8 + kbA];
                al[mt][2] = Hl[r0 + kbA + 4]; al[mt][3] = Hl[r8 + kbA + 4];
            }
            #pragma unroll
            for (int nt = 0; nt < 8; nt++) {
                int nr = (half*64 + nt*8 + g)*CPAD;
                uint32_t bh0 = Wth[nr + kbW], bh1 = Wth[nr + kbW + 4];
                uint32_t bl0 = Wtl[nr + kbW], bl1 = Wtl[nr + kbW + 4];
                #pragma unroll
                for (int mt = 0; mt < 2; mt++) {
                    mma_f16(acc[mt][nt], ah[mt][0], ah[mt][1], ah[mt][2], ah[mt][3], bh0, bh1);
                    mma_f16(acc[mt][nt], ah[mt][0], ah[mt][1], ah[mt][2], ah[mt][3], bl0, bl1);
                    mma_f16(acc[mt][nt], al[mt][0], al[mt][1], al[mt][2], al[mt][3], bh0, bh1);
                }
            }
        }
    }

    bool writer = ((g & 1) == 0);
    #pragma unroll
    for (int mt = 0; mt < 2; mt++)
        #pragma unroll
        for (int nt = 0; nt < 8; nt++) {
            float c0 = acc[mt][nt][0], c1 = acc[mt][nt][1];
            float c2 = acc[mt][nt][2], c3 = acc[mt][nt][3];
            c0 = fmaxf(c0, __shfl_xor_sync(0xffffffffu, c0, 4));
            c1 = fmaxf(c1, __shfl_xor_sync(0xffffffffu, c1, 4));
            c2 = fmaxf(c2, __shfl_xor_sync(0xffffffffu, c2, 4));
            c3 = fmaxf(c3, __shfl_xor_sync(0xffffffffu, c3, 4));
            int col = half*64 + nt*8 + 2*tig;
            float bb0 = b2s[col], bb1 = b2s[col+1];
            if (writer) {
                int p0 = (m0 + band*32 + mt*16 + g) >> 1;
                float o00 = fmaxf(c0 + bb0, 0.f), o01 = fmaxf(c1 + bb1, 0.f);
                float o10 = fmaxf(c2 + bb0, 0.f), o11 = fmaxf(c3 + bb1, 0.f);
                *(float2*)(yout + (size_t)p0*128 + col) = make_float2(o00, o01);
                *(float2*)(yout + (size_t)(p0 + 4)*128 + col) = make_float2(o10, o11);
                uint32_t hw, lw;
                f16_split2(o00, o01, hw, lw);
                yhout[(size_t)p0*64 + (col >> 1)] = hw;
                ylout[(size_t)p0*64 + (col >> 1)] = lw;
                f16_split2(o10, o11, hw, lw);
                yhout[(size_t)(p0 + 4)*64 + (col >> 1)] = hw;
                ylout[(size_t)(p0 + 4)*64 + (col >> 1)] = lw;
            }
        }
}

// ======= conv2/3 (HMMA f16): gather edge(256) @ W(256x128) -> relu+max-k ===
#define CB_EH 0
#define CB_EL 18432
#define CB_WH 36864
#define CB_WL 55296
#define CB_BIAS 73728
#define CB_IDX  74240
#define CB_SMEM 74752

__global__ void __launch_bounds__(256, 2)
convB_mma_kernel(const float* __restrict__ yin,
                 const uint32_t* __restrict__ yhin, const uint32_t* __restrict__ ylin,
                 const int* __restrict__ idxg,
                 const uint32_t* __restrict__ cwh, const uint32_t* __restrict__ cwl,
                 const float* __restrict__ bias,
                 float* __restrict__ yout,
                 uint32_t* __restrict__ yhout, uint32_t* __restrict__ ylout) {
    extern __shared__ char smem[];
    uint32_t* Eh  = (uint32_t*)(smem + CB_EH);
    uint32_t* El  = (uint32_t*)(smem + CB_EL);
    uint32_t* Wth = (uint32_t*)(smem + CB_WH);
    uint32_t* Wtl = (uint32_t*)(smem + CB_WL);
    float* sbias = (float*)(smem + CB_BIAS);
    int*   sidx  = (int*)(smem + CB_IDX);

    int tid = threadIdx.x, lane = tid & 31, wid = tid >> 5;
    int g = lane >> 2, tig = lane & 3;
    int band = wid & 3, half = wid >> 2;
    int m0 = blockIdx.x*128;
    int bbase = ((m0 >> 1) >> 10) << 10;
    if (tid < 128) { sidx[tid] = idxg[m0 + tid]; sbias[tid] = bias[tid]; }

    float acc[2][8][4];
    #pragma unroll
    for (int mt = 0; mt < 2; mt++)
        #pragma unroll
        for (int nt = 0; nt < 8; nt++)
            #pragma unroll
            for (int q = 0; q < 4; q++) acc[mt][nt][q] = 0.f;

    for (int kc = 0; kc < 256; kc += 64) {
        __syncthreads();
        {
            bool ipart = kc < 128;
            if (ipart) {
                int kpb = kc >> 1;
                for (int v = tid; v < 128*32; v += 256) {
                    int r = v >> 5, kp = v & 31;
                    int ig = (m0 + r) >> 1;
                    Eh[r*CPAD + kp] = yhin[(size_t)ig*64 + kpb + kp];
                    El[r*CPAD + kp] = ylin[(size_t)ig*64 + kpb + kp];
                }
            } else {
                int fb = kc - 128;
                for (int v = tid; v < 128*32; v += 256) {
                    int r = v >> 5, kp = v & 31;
                    int ig = (m0 + r) >> 1;
                    int jg = bbase + sidx[r];
                    float2 xv = *(const float2*)(yin + (size_t)ig*128 + fb + 2*kp);
                    float2 bj = *(const float2*)(yin + (size_t)jg*128 + fb + 2*kp);
                    uint32_t hw, lw; f16_split2(bj.x - xv.x, bj.y - xv.y, hw, lw);
                    Eh[r*CPAD + kp] = hw; El[r*CPAD + kp] = lw;
                }
            }
        }
        {
            int kpb = kc >> 1;
            for (int v = tid; v < 128*32; v += 256) {
                int n = v >> 5, kp = v & 31;
                Wth[n*CPAD + kp] = cwh[n*128 + kpb + kp];
                Wtl[n*CPAD + kp] = cwl[n*128 + kpb + kp];
            }
        }
        __syncthreads();

        #pragma unroll
        for (int ks = 0; ks < 4; ks++) {
            int kb = ks*8 + tig;
            uint32_t ah[2][4], al[2][4];
            #pragma unroll
            for (int mt = 0; mt < 2; mt++) {
                int r0 = (band*32 + mt*16 + g)*CPAD;
                int r8 = r0 + 8*CPAD;
                ah[mt][0] = Eh[r0 + kb];     ah[mt][1] = Eh[r8 + kb];
                ah[mt][2] = Eh[r0 + kb + 4]; ah[mt][3] = Eh[r8 + kb + 4];
                al[mt][0] = El[r0 + kb];     al[mt][1] = El[r8 + kb];
                al[mt][2] = El[r0 + kb + 4]; al[mt][3] = El[r8 + kb + 4];
            }
            #pragma unroll
            for (int nt = 0; nt < 8; nt++) {
                int nr = (half*64 + nt*8 + g)*CPAD;
                uint32_t bh0 = Wth[nr + kb], bh1 = Wth[nr + kb + 4];
                uint32_t bl0 = Wtl[nr + kb], bl1 = Wtl[nr + kb + 4];
                #pragma unroll
                for (int mt = 0; mt < 2; mt++) {
                    mma_f16(acc[mt][nt], ah[mt][0], ah[mt][1], ah[mt][2], ah[mt][3], bh0, bh1);
                    mma_f16(acc[mt][nt], ah[mt][0], ah[mt][1], ah[mt][2], ah[mt][3], bl0, bl1);
                    mma_f16(acc[mt][nt], al[mt][0], al[mt][1], al[mt][2], al[mt][3], bh0, bh1);
                }
            }
        }
    }

    bool writer = ((g & 1) == 0);
    #pragma unroll
    for (int mt = 0; mt < 2; mt++)
        #pragma unroll
        for (int nt = 0; nt < 8; nt++) {
            float c0 = acc[mt][nt][0], c1 = acc[mt][nt][1];
            float c2 = acc[mt][nt][2], c3 = acc[mt][nt][3];
            c0 = fmaxf(c0, __shfl_xor_sync(0xffffffffu, c0, 4));
            c1 = fmaxf(c1, __shfl_xor_sync(0xffffffffu, c1, 4));
            c2 = fmaxf(c2, __shfl_xor_sync(0xffffffffu, c2, 4));
            c3 = fmaxf(c3, __shfl_xor_sync(0xffffffffu, c3, 4));
            int col = half*64 + nt*8 + 2*tig;
            float bb0 = sbias[col], bb1 = sbias[col+1];
            if (writer) {
                int p0 = (m0 + band*32 + mt*16 + g) >> 1;
                float o00 = fmaxf(c0 + bb0, 0.f), o01 = fmaxf(c1 + bb1, 0.f);
                float o10 = fmaxf(c2 + bb0, 0.f), o11 = fmaxf(c3 + bb1, 0.f);
                *(float2*)(yout + (size_t)p0*128 + col) = make_float2(o00, o01);
                *(float2*)(yout + (size_t)(p0 + 4)*128 + col) = make_float2(o10, o11);
                uint32_t hw, lw;
                f16_split2(o00, o01, hw, lw);
                yhout[(size_t)p0*64 + (col >> 1)] = hw;
                ylout[(size_t)p0*64 + (col >> 1)] = lw;
                f16_split2(o10, o11, hw, lw);
                yhout[(size_t)(p0 + 4)*64 + (col >> 1)] = hw;
                ylout[(size_t)(p0 + 4)*64 + (col >> 1)] = lw;
            }
        }
}

// ------------------------------------------------ mean/max pool over nodes
__global__ void __launch_bounds__(128) pool_kernel(const float* __restrict__ y1,
                                                   const float* __restrict__ y2,
                                                   const float* __restrict__ y3,
                                                   float* __restrict__ g) {
    int b = blockIdx.x, s = blockIdx.y, t = threadIdx.x;
    const float* src = (s == 0) ? y1 : ((s == 1) ? y2 : y3);
    const float* p = src + (size_t)b*NN*WW + t;
    float sum = 0.f, mx = -CUDART_INF_F;
    #pragma unroll 4
    for (int n = 0; n < NN; n++) {
        float v = p[(size_t)n*WW];
        sum += v; mx = fmaxf(mx, v);
    }
    int c = s*WW + t;
    g[b*DD2 + c]       = sum * (1.f/1024.f);
    g[b*DD2 + 384 + c] = mx;
}

// --------------------------------- batchnorm (batch stats), 6-block split
__global__ void __launch_bounds__(128) bn_kernel(const float* __restrict__ g,
                                                 const float* __restrict__ gam,
                                                 const float* __restrict__ bet,
                                                 float* __restrict__ h) {
    int c = blockIdx.x*128 + threadIdx.x;
    float mu = 0.f;
    for (int b = 0; b < BB; b++) mu += g[b*DD2 + c];
    mu *= (1.f/64.f);
    float var = 0.f;
    for (int b = 0; b < BB; b++) { float d = g[b*DD2 + c] - mu; var += d*d; }
    var *= (1.f/64.f);
    float sc = rsqrtf(var + 1e-5f) * gam[c];
    float be = bet[c];
    for (int b = 0; b < BB; b++)
        h[b*DD2 + c] = (g[b*DD2 + c] - mu)*sc + be;
}

// --------------------------------------------- 768x768 linear + leaky relu
__global__ void __launch_bounds__(128) linear_kernel(const float* __restrict__ hin,
                                                     const float* __restrict__ Wt,
                                                     const float* __restrict__ bias,
                                                     float* __restrict__ hout) {
    __shared__ float sh[DD2];
    int b = blockIdx.x;
    for (int v = threadIdx.x; v < DD2; v += 128) sh[v] = hin[b*DD2 + v];
    __syncthreads();
    int o = blockIdx.y*128 + threadIdx.x;
    float acc = bias[o];
    #pragma unroll 8
    for (int k = 0; k < DD2; k++) acc += sh[k]*Wt[(size_t)k*DD2 + o];
    acc = (acc >= 0.f) ? acc : 0.01f*acc;
    hout[b*DD2 + o] = acc;
}

// ------------------------------------------------------------ output layer
__global__ void __launch_bounds__(256) out_kernel(const float* __restrict__ h,
                                                  const float* __restrict__ ow,
                                                  const float* __restrict__ ob,
                                                  float* __restrict__ out) {
    __shared__ float red[256];
    int b = blockIdx.x;
    float acc = 0.f;
    for (int k = threadIdx.x; k < DD2; k += 256) acc += h[b*DD2 + k]*ow[k];
    red[threadIdx.x] = acc;
    __syncthreads();
    for (int s = 128; s; s >>= 1) {
        if (threadIdx.x < s) red[threadIdx.x] += red[threadIdx.x + s];
        __syncthreads();
    }
    if (threadIdx.x == 0) out[b] = red[0] + ob[0];
}

// --------------------------------------------------------------------- host
extern "C" void kernel_launch(void* const* d_in, const int* in_sizes, int n_in,
                              void* d_out, int out_size) {
    (void)in_sizes; (void)n_in; (void)out_size;
    const float* x     = (const float*)d_in[0];
    const float* p1_w1 = (const float*)d_in[1];
    const float* p1_b1 = (const float*)d_in[2];
    const float* p1_w2 = (const float*)d_in[3];
    const float* p1_b2 = (const float*)d_in[4];
    const float* c_w   = (const float*)d_in[5];
    const float* c_b   = (const float*)d_in[6];
    const float* bng   = (const float*)d_in[7];
    const float* bnb   = (const float*)d_in[8];
    const float* lin_w = (const float*)d_in[9];
    const float* lin_b = (const float*)d_in[10];
    const float* out_w = (const float*)d_in[11];
    const float* out_b = (const float*)d_in[12];
    float* out = (float*)d_out;

    float *y1, *y2, *y3, *sq, *gg, *hA, *hB; int* idx;
    uint32_t *yh, *yl, *cwh, *cwl;
    cudaGetSymbolAddress((void**)&y1, d_y1);
    cudaGetSymbolAddress((void**)&y2, d_y2);
    cudaGetSymbolAddress((void**)&y3, d_y3);
    cudaGetSymbolAddress((void**)&yh, d_yh);
    cudaGetSymbolAddress((void**)&yl, d_yl);
    cudaGetSymbolAddress((void**)&sq, d_sq);
    cudaGetSymbolAddress((void**)&gg, d_g);
    cudaGetSymbolAddress((void**)&hA, d_hA);
    cudaGetSymbolAddress((void**)&hB, d_hB);
    cudaGetSymbolAddress((void**)&idx, d_idx);
    cudaGetSymbolAddress((void**)&cwh, d_cwh);
    cudaGetSymbolAddress((void**)&cwl, d_cwl);

    const size_t YSP = (size_t)BB*NN*64;   // per-buffer size of yh/yl

    cudaFuncSetAttribute((const void*)knn128_mma_kernel,
                         cudaFuncAttributeMaxDynamicSharedMemorySize, KNNMMA_SMEM);
    cudaFuncSetAttribute((const void*)convAF_mma_kernel,
                         cudaFuncAttributeMaxDynamicSharedMemorySize, AF_SMEM);
    cudaFuncSetAttribute((const void*)convB_mma_kernel,
                         cudaFuncAttributeMaxDynamicSharedMemorySize, CB_SMEM);

    prep_conv_kernel<<<(128*64 + 2*128*128)/256, 256>>>(p1_w2, c_w);

    knn5_kernel  <<<dim3(4, BB), 256>>>(x, idx);
    convAF_mma_kernel<<<MTOT/128, 256, AF_SMEM>>>(x, idx, p1_w1, p1_b1, p1_b2,
                                                  y1, yh, yl);

    sqnorm_kernel<<<(BB*NN)/8, 256>>>(y1, sq);
    knn128_mma_kernel<<<dim3(NN/128, BB), 256, KNNMMA_SMEM>>>(yh, yl, y1, sq, idx);
    convB_mma_kernel<<<MTOT/128, 256, CB_SMEM>>>(y1, yh, yl, idx, cwh, cwl, c_b,
                                                 y2, yh + YSP, yl + YSP);

    sqnorm_kernel<<<(BB*NN)/8, 256>>>(y2, sq);
    knn128_mma_kernel<<<dim3(NN/128, BB), 256, KNNMMA_SMEM>>>(yh + YSP, yl + YSP,
                                                              y2, sq, idx);
    convB_mma_kernel<<<MTOT/128, 256, CB_SMEM>>>(y2, yh + YSP, yl + YSP, idx,
                                                 cwh + 16384, cwl + 16384,
                                                 c_b + 128, y3, yh, yl);

    pool_kernel<<<dim3(BB, 3), 128>>>(y1, y2, y3, gg);
    bn_kernel  <<<6, 128>>>(gg, bng, bnb, hA);

    const float* lin_in = hA; float* lin_out = hB;
    for (int l = 0; l < 5; l++) {
        linear_kernel<<<dim3(BB, DD2/128), 128>>>(lin_in,
                                                  lin_w + (size_t)l*DD2*DD2,
                                                  lin_b + l*DD2, lin_out);
        const float* t = lin_in; lin_in = lin_out; lin_out = (float*)t;
    }
    out_kernel<<<BB, 256>>>(lin_in, out_w, out_b, out);
}

// round 15
// speedup vs baseline: 1.2843x; 1.2443x over previous
#include <cuda_runtime.h>
#include <cuda_fp16.h>
#include <math_constants.h>
#include <cstdint>
#include <cstddef>

#define BB   64
#define NN   1024
#define FF   5
#define WW   128
#define KNN  2
#define DD2  768
#define MTOT (BB*NN*KNN)   // 131072 edge rows

// ------------------------------------------------------------------ scratch
__device__ float d_y1[(size_t)BB*NN*WW];
__device__ float d_y2[(size_t)BB*NN*WW];
__device__ float d_y3[(size_t)BB*NN*WW];
__device__ uint32_t d_yh[2][(size_t)BB*NN*64];
__device__ uint32_t d_yl[2][(size_t)BB*NN*64];
__device__ float d_sq[BB*NN];
__device__ int   d_idx[MTOT];
__device__ float d_g [BB*DD2];
__device__ float d_hA[BB*DD2];
__device__ float d_hB[BB*DD2];
// pre-split conv weights. convB weights are TRANSFORMED: W' = [Wtop-Wbot; Wbot]
// so that E' = [yi ; yj] (both available pre-split) gives identical output.
__device__ uint32_t d_w2h[128*64],  d_w2l[128*64];       // convAF W2: [n][kp]
__device__ uint32_t d_cwh[2*128*128], d_cwl[2*128*128];  // convB W': [f][n][kp]

// ---------------------------------------------------------------- utilities
__device__ __forceinline__ bool lessdj(float d, int j, float D, int J) {
    return d < D || (d == D && j < J);
}
// strict-< insertion: stable, so ascending-j insert order == lower-index tiebreak
__device__ __forceinline__ void ins3f(float nd, int nj,
                                      float& D1, int& J1, float& D2, int& J2,
                                      float& D3, int& J3) {
    if (nd < D3) {
        if (nd < D2) {
            D3 = D2; J3 = J2;
            if (nd < D1) { D2 = D1; J2 = J1; D1 = nd; J1 = nj; }
            else { D2 = nd; J2 = nj; }
        } else { D3 = nd; J3 = nj; }
    }
}
__device__ __forceinline__ void ins3dj(float nd, int nj,
                                       float& D1, int& J1, float& D2, int& J2,
                                       float& D3, int& J3) {
    if (lessdj(nd, nj, D3, J3)) {
        if (lessdj(nd, nj, D2, J2)) {
            D3 = D2; J3 = J2;
            if (lessdj(nd, nj, D1, J1)) { D2 = D1; J2 = J1; D1 = nd; J1 = nj; }
            else { D2 = nd; J2 = nj; }
        } else { D3 = nd; J3 = nj; }
    }
}
__device__ __forceinline__ void f16_split2(float x0, float x1,
                                           uint32_t& hw, uint32_t& lw) {
    __half h0 = __float2half_rn(x0);
    __half h1 = __float2half_rn(x1);
    float r0 = x0 - __half2float(h0);
    float r1 = x1 - __half2float(h1);
    __half l0 = __float2half_rn(r0);
    __half l1 = __float2half_rn(r1);
    hw = ((uint32_t)__half_as_ushort(h1) << 16) | (uint32_t)__half_as_ushort(h0);
    lw = ((uint32_t)__half_as_ushort(l1) << 16) | (uint32_t)__half_as_ushort(l0);
}
__device__ __forceinline__ void mma_f16(float c[4], uint32_t a0, uint32_t a1,
                                        uint32_t a2, uint32_t a3,
                                        uint32_t b0, uint32_t b1) {
    asm volatile(
        "mma.sync.aligned.m16n8k16.row.col.f32.f16.f16.f32 "
        "{%0,%1,%2,%3}, {%4,%5,%6,%7}, {%8,%9}, {%0,%1,%2,%3};"
        : "+f"(c[0]), "+f"(c[1]), "+f"(c[2]), "+f"(c[3])
        : "r"(a0), "r"(a1), "r"(a2), "r"(a3), "r"(b0), "r"(b1));
}
__device__ __forceinline__ void ldsm_x4(uint32_t r[4], uint32_t addr) {
    asm volatile("ldmatrix.sync.aligned.m8n8.x4.shared.b16 {%0,%1,%2,%3}, [%4];"
                 : "=r"(r[0]), "=r"(r[1]), "=r"(r[2]), "=r"(r[3]) : "r"(addr));
}
__device__ __forceinline__ uint32_t smem_u32(const void* p) {
    uint32_t a;
    asm("{ .reg .u64 t; cvta.to.shared.u64 t, %1; cvt.u32.u64 %0, t; }"
        : "=r"(a) : "l"(p));
    return a;
}
__device__ __forceinline__ void cp16(uint32_t dst, const void* src) {
    asm volatile("cp.async.cg.shared.global [%0], [%1], 16;"
                 :: "r"(dst), "l"(src) : "memory");
}
#define CP_COMMIT() asm volatile("cp.async.commit_group;" ::: "memory")
#define CP_WAIT0()  asm volatile("cp.async.wait_group 0;" ::: "memory")

// ---------------------------------------------------------- weight presplit
__global__ void __launch_bounds__(256) prep_conv_kernel(const float* __restrict__ W2,
                                                        const float* __restrict__ cw) {
    int idx = blockIdx.x*256 + threadIdx.x;
    if (idx < 128*64) {
        int kp = idx & 63, n = idx >> 6;
        uint32_t hw, lw;
        f16_split2(W2[(size_t)(2*kp)*128 + n], W2[(size_t)(2*kp+1)*128 + n], hw, lw);
        d_w2h[n*64 + kp] = hw; d_w2l[n*64 + kp] = lw;
    } else {
        int i2 = idx - 128*64;          // < 2*128*128
        int f = i2 >> 14, rem = i2 & 16383;
        int kp = rem & 127, n = rem >> 7;
        const float* wb = cw + (size_t)f*256*128;
        float v0, v1;
        if (kp < 64) {                  // W'top = Wtop - Wbot (exact fp32)
            int k = 2*kp;
            v0 = wb[(size_t)k*128 + n]     - wb[(size_t)(k+128)*128 + n];
            v1 = wb[(size_t)(k+1)*128 + n] - wb[(size_t)(k+129)*128 + n];
        } else {                        // W'bot = Wbot
            int k2 = 2*(kp - 64);
            v0 = wb[(size_t)(128 + k2)*128 + n];
            v1 = wb[(size_t)(129 + k2)*128 + n];
        }
        uint32_t hw, lw;
        f16_split2(v0, v1, hw, lw);
        d_cwh[f*16384 + n*128 + kp] = hw;
        d_cwl[f*16384 + n*128 + kp] = lw;
    }
}

// ------------------------------------------------------------ knn on x (D=5)
__global__ void __launch_bounds__(256) knn5_kernel(const float* __restrict__ x,
                                                   int* __restrict__ idx) {
    __shared__ float sx[NN*FF];
    __shared__ float ssq[NN];
    int b = blockIdx.y;
    const float* xb = x + (size_t)b*NN*FF;
    for (int v = threadIdx.x; v < NN*FF; v += 256) sx[v] = xb[v];
    __syncthreads();
    for (int v = threadIdx.x; v < NN; v += 256) {
        float s = 0.f;
        #pragma unroll
        for (int f = 0; f < FF; f++) { float t = sx[v*FF+f]; s += t*t; }
        ssq[v] = s;
    }
    __syncthreads();
    int i = blockIdx.x*256 + threadIdx.x;
    float xi[FF];
    #pragma unroll
    for (int f = 0; f < FF; f++) xi[f] = sx[i*FF+f];
    float sqi = ssq[i];
    float d1 = CUDART_INF_F, d2 = CUDART_INF_F;
    int j1 = 0, j2 = 0;
    for (int j = 0; j < NN; j++) {
        float dot = 0.f;
        #pragma unroll
        for (int f = 0; f < FF; f++) dot += xi[f]*sx[j*FF+f];
        float d = sqi + ssq[j] - 2.f*dot;
        if (d < d1)      { d2 = d1; j2 = j1; d1 = d; j1 = j; }
        else if (d < d2) { d2 = d;  j2 = j; }
    }
    int m = (b*NN + i)*KNN;
    idx[m] = j1; idx[m+1] = j2;
}

// --------------------------------------------------------------- sq norms
__global__ void __launch_bounds__(256) sqnorm_kernel(const float* __restrict__ y,
                                                     float* __restrict__ sq) {
    int w = threadIdx.x >> 5, lane = threadIdx.x & 31;
    int p = blockIdx.x*8 + w;
    const float* yp = y + (size_t)p*WW;
    float s = 0.f;
    #pragma unroll
    for (int c = 0; c < 4; c++) { float v = yp[lane + 32*c]; s += v*v; }
    #pragma unroll
    for (int o = 16; o; o >>= 1) s += __shfl_xor_sync(0xffffffffu, s, o);
    if (lane == 0) sq[p] = s;
}

// == knn on y (D=128): f16 3-term HMMA + cp.async ping-pong,
//    plain-< top-3/thread, merge-free 24-candidate epilogue
#define OFF_AH 0
#define OFF_AL 34816
#define OFF_BP 69632
#define OFF_SQB 104448
#define KNNMMA_SMEM 104704

__global__ void __launch_bounds__(256, 2)
knn128_mma_kernel(const uint32_t* __restrict__ yh,
                  const uint32_t* __restrict__ yl,
                  const float* __restrict__ y,
                  const float* __restrict__ sq,
                  int* __restrict__ idx) {
    extern __shared__ char smem[];
    uint32_t* Ah = (uint32_t*)(smem + OFF_AH);
    uint32_t* Al = (uint32_t*)(smem + OFF_AL);
    float* cf    = (float*)(smem + OFF_BP);          // overlay: 128x24 dists
    int*   ci    = (int*)(smem + OFF_BP + 12288);    // overlay: 128x24 idx
    uint32_t smb = smem_u32(smem);

    int tid = threadIdx.x, wid = tid >> 5, lane = tid & 31;
    int g = lane >> 2, tig = lane & 3;
    int band = wid & 3, half = wid >> 2;
    int b = blockIdx.y, i0 = blockIdx.x*128;
    const float* yb  = y + (size_t)b*NN*WW;
    const float* sqb = sq + b*NN;
    const uint4* yh4 = (const uint4*)(yh + (size_t)b*NN*64);
    const uint4* yl4 = (const uint4*)(yl + (size_t)b*NN*64);

    int mA = lane >> 3, rA = lane & 7;
    uint32_t aAddr = smb + OFF_AH +
        (uint32_t)(((band*32 + (mA & 1)*8 + rA)*68 + (mA >> 1)*4) * 4);
    uint32_t bOff =
        (uint32_t)(((half*16 + (mA >> 1)*8 + rA)*68 + (mA & 1)*4) * 4);

    for (int v = tid; v < 2048; v += 256) {
        int r = v >> 4, q = v & 15;
        *(uint4*)(Ah + r*68 + q*4) = yh4[(size_t)(i0+r)*16 + q];
        *(uint4*)(Al + r*68 + q*4) = yl4[(size_t)(i0+r)*16 + q];
    }

    auto issueB = [&](int ch) {
        int p = ch & 1;
        uint32_t base = smb + OFF_BP + (uint32_t)(p*17408);
        int jt = ch*32;
        #pragma unroll
        for (int w = 0; w < 4; w++) {
            int v = tid + w*256;
            int arr = v >> 9, r = (v >> 4) & 31, q = v & 15;
            uint32_t dst = base + (uint32_t)(arr*8704 + (r*68 + q*4)*4);
            const uint4* src = (arr ? yl4 : yh4) + (size_t)(jt + r)*16 + q;
            cp16(dst, src);
        }
        if (tid < 8)
            cp16(smb + OFF_SQB + (uint32_t)(p*128 + tid*16), sqb + jt + tid*4);
    };

    issueB(0);
    CP_COMMIT();

    float sqAr[4];
    #pragma unroll
    for (int s = 0; s < 4; s++)
        sqAr[s] = sqb[i0 + band*32 + g + (s >> 1)*16 + (s & 1)*8];

    float D1[4], D2[4], D3[4]; int J1[4], J2[4], J3[4];
    #pragma unroll
    for (int s = 0; s < 4; s++) {
        D1[s] = CUDART_INF_F; D2[s] = CUDART_INF_F; D3[s] = CUDART_INF_F;
        J1[s] = 0x7fffffff;   J2[s] = 0x7fffffff;   J3[s] = 0x7fffffff;
    }

    for (int ch = 0; ch < 32; ch++) {
        CP_WAIT0();
        __syncthreads();
        if (ch + 1 < 32) { issueB(ch + 1); CP_COMMIT(); }

        uint32_t bb = smb + OFF_BP + (uint32_t)((ch & 1)*17408);
        int jt = ch*32;

        float acc[2][2][4];
        #pragma unroll
        for (int mt = 0; mt < 2; mt++)
            #pragma unroll
            for (int t = 0; t < 2; t++)
                #pragma unroll
                for (int q = 0; q < 4; q++) acc[mt][t][q] = 0.f;

        #pragma unroll
        for (int ks = 0; ks < 8; ks++) {
            uint32_t ah0[4], ah1[4], al0[4], al1[4], bh[4], bl[4];
            ldsm_x4(ah0, aAddr + ks*32);
            ldsm_x4(ah1, aAddr + 4352 + ks*32);
            ldsm_x4(al0, aAddr + 34816 + ks*32);
            ldsm_x4(al1, aAddr + 34816 + 4352 + ks*32);
            ldsm_x4(bh, bb + bOff + ks*32);
            ldsm_x4(bl, bb + 8704 + bOff + ks*32);
            #pragma unroll
            for (int t = 0; t < 2; t++) {
                uint32_t b0h = bh[2*t], b1h = bh[2*t+1];
                uint32_t b0l = bl[2*t], b1l = bl[2*t+1];
                mma_f16(acc[0][t], ah0[0], ah0[1], ah0[2], ah0[3], b0h, b1h);
                mma_f16(acc[0][t], ah0[0], ah0[1], ah0[2], ah0[3], b0l, b1l);
                mma_f16(acc[0][t], al0[0], al0[1], al0[2], al0[3], b0h, b1h);
                mma_f16(acc[1][t], ah1[0], ah1[1], ah1[2], ah1[3], b0h, b1h);
                mma_f16(acc[1][t], ah1[0], ah1[1], ah1[2], ah1[3], b0l, b1l);
                mma_f16(acc[1][t], al1[0], al1[1], al1[2], al1[3], b0h, b1h);
            }
        }

        const float* sqBs = (const float*)(smem + OFF_SQB + (ch & 1)*128);
        #pragma unroll
        for (int s = 0; s < 4; s++) {
            int mt = s >> 1, q0 = (s & 1)*2;
            int jl = half*16 + 2*tig;
            int jb = jt + jl;
            float v0 = fmaf(-2.f, acc[mt][0][q0],   sqAr[s] + sqBs[jl]);
            float v1 = fmaf(-2.f, acc[mt][0][q0+1], sqAr[s] + sqBs[jl + 1]);
            float v2 = fmaf(-2.f, acc[mt][1][q0],   sqAr[s] + sqBs[jl + 8]);
            float v3 = fmaf(-2.f, acc[mt][1][q0+1], sqAr[s] + sqBs[jl + 9]);
            ins3f(v0, jb,     D1[s], J1[s], D2[s], J2[s], D3[s], J3[s]);
            ins3f(v1, jb + 1, D1[s], J1[s], D2[s], J2[s], D3[s], J3[s]);
            ins3f(v2, jb + 8, D1[s], J1[s], D2[s], J2[s], D3[s], J3[s]);
            ins3f(v3, jb + 9, D1[s], J1[s], D2[s], J2[s], D3[s], J3[s]);
        }
    }

    // NO cross-thread merge: 8 threads/row x top-3 -> 24 candidates/row
    __syncthreads();
    {
        int thr = half*4 + tig;
        #pragma unroll
        for (int s = 0; s < 4; s++) {
            int row = band*32 + g + (s >> 1)*16 + (s & 1)*8;
            int base = row*24 + thr*3;
            cf[base + 0] = D1[s]; ci[base + 0] = J1[s];
            cf[base + 1] = D2[s]; ci[base + 1] = J2[s];
            cf[base + 2] = D3[s]; ci[base + 2] = J3[s];
        }
    }
    __syncthreads();

    if (tid < 128) {
        int row = tid;
        float m0 = CUDART_INF_F, m1 = CUDART_INF_F, m2 = CUDART_INF_F;
        int n0 = 0x7fffffff, n1 = 0x7fffffff, n2 = 0x7fffffff;
        #pragma unroll
        for (int q = 0; q < 24; q++) {
            float d = cf[row*24 + q]; int j = ci[row*24 + q];
            ins3dj(d, j, m0, n0, m1, n1, m2, n2);
        }
        int o1 = n0, o2 = n1;
        if (m2 - m1 < 4e-3f) {
            float sqi = sqb[i0 + row];
            const float4* a4 = (const float4*)(yb + (size_t)(i0 + row)*WW);
            float e1 = CUDART_INF_F, e2 = CUDART_INF_F;
            int f1 = 0x7fffffff, f2 = 0x7fffffff;
            for (int q = 0; q < 24; q++) {
                int j = ci[row*24 + q];
                if (j == 0x7fffffff) continue;
                const float4* b4 = (const float4*)(yb + (size_t)j*WW);
                float dot = 0.f;
                #pragma unroll
                for (int k = 0; k < 32; k++) {
                    float4 av = a4[k], bv = b4[k];
                    dot += av.x*bv.x + av.y*bv.y + av.z*bv.z + av.w*bv.w;
                }
                float d = sqi + sqb[j] - 2.f*dot;
                if (lessdj(d, j, e1, f1))      { e2 = e1; f2 = f1; e1 = d; f1 = j; }
                else if (lessdj(d, j, e2, f2)) { e2 = d; f2 = j; }
            }
            o1 = f1; o2 = f2;
        }
        int m = (b*NN + i0 + row)*KNN;
        idx[m] = o1; idx[m+1] = o2;
    }
}

// ====== conv1 FUSED (HMMA f16): edge(10)->relu h1(128) -> @W2 -> relu+max-k
#define CPAD 36
#define APAD 68
#define AF_HH 0
#define AF_HL 34816
#define AF_WH 69632
#define AF_WL 88064
#define AF_W1 106496
#define AF_B1 111616
#define AF_B2 112128
#define AF_IDX 112640
#define AF_SMEM 113152

__global__ void __launch_bounds__(256, 2)
convAF_mma_kernel(const float* __restrict__ x, const int* __restrict__ idxg,
                  const float* __restrict__ W1, const float* __restrict__ b1,
                  const float* __restrict__ b2,
                  float* __restrict__ yout,
                  uint32_t* __restrict__ yhout, uint32_t* __restrict__ ylout) {
    extern __shared__ char smem[];
    uint32_t* Hh  = (uint32_t*)(smem + AF_HH);
    uint32_t* Hl  = (uint32_t*)(smem + AF_HL);
    uint32_t* Wth = (uint32_t*)(smem + AF_WH);
    uint32_t* Wtl = (uint32_t*)(smem + AF_WL);
    float* w1s = (float*)(smem + AF_W1);
    float* b1s = (float*)(smem + AF_B1);
    float* b2s = (float*)(smem + AF_B2);
    int*   sidx = (int*)(smem + AF_IDX);

    int tid = threadIdx.x, lane = tid & 31, wid = tid >> 5;
    int g = lane >> 2, tig = lane & 3;
    int band = wid & 3, half = wid >> 2;
    int m0 = blockIdx.x*128;

    for (int v = tid; v < 10*128; v += 256) w1s[v] = W1[v];
    if (tid < 128) { b1s[tid] = b1[tid]; b2s[tid] = b2[tid]; sidx[tid] = idxg[m0 + tid]; }
    __syncthreads();

    {
        int r = tid >> 1;
        int m = m0 + r;
        int pg = m >> 1;
        int b  = pg >> 10;
        int j  = sidx[r];
        const float* xi = x + (size_t)pg*FF;
        const float* xj = x + ((size_t)b*NN + j)*FF;
        float e[10];
        #pragma unroll
        for (int f = 0; f < FF; f++) {
            float a = xi[f];
            e[f] = a; e[FF+f] = xj[f] - a;
        }
        int kpbase = (tid & 1)*32;
        #pragma unroll 2
        for (int q = 0; q < 32; q++) {
            int c0 = 2*(kpbase + q);
            float a0 = b1s[c0], a1 = b1s[c0+1];
            #pragma unroll
            for (int f = 0; f < 10; f++) {
                a0 += e[f]*w1s[f*128 + c0];
                a1 += e[f]*w1s[f*128 + c0 + 1];
            }
            a0 = fmaxf(a0, 0.f); a1 = fmaxf(a1, 0.f);
            uint32_t hw, lw; f16_split2(a0, a1, hw, lw);
            Hh[r*APAD + kpbase + q] = hw;
            Hl[r*APAD + kpbase + q] = lw;
        }
    }

    float acc[2][8][4];
    #pragma unroll
    for (int mt = 0; mt < 2; mt++)
        #pragma unroll
        for (int nt = 0; nt < 8; nt++)
            #pragma unroll
            for (int q = 0; q < 4; q++) acc[mt][nt][q] = 0.f;

    for (int chk = 0; chk < 2; chk++) {
        __syncthreads();
        for (int v = tid; v < 128*32; v += 256) {
            int n = v >> 5, kp = v & 31;
            Wth[n*CPAD + kp] = d_w2h[n*64 + chk*32 + kp];
            Wtl[n*CPAD + kp] = d_w2l[n*64 + chk*32 + kp];
        }
        __syncthreads();

        #pragma unroll
        for (int ks = 0; ks < 4; ks++) {
            int kbA = chk*32 + ks*8 + tig;
            int kbW = ks*8 + tig;
            uint32_t ah[2][4], al[2][4];
            #pragma unroll
            for (int mt = 0; mt < 2; mt++) {
                int r0 = (band*32 + mt*16 + g)*APAD;
                int r8 = r0 + 8*APAD;
                ah[mt][0] = Hh[r0 + kbA];     ah[mt][1] = Hh[r8 + kbA];
                ah[mt][2] = Hh[r0 + kbA + 4]; ah[mt][3] = Hh[r8 + kbA + 4];
                al[mt][0] = Hl[r0 + kbA];     al[mt][1] = Hl[r8 + kbA];
                al[mt][2] = Hl[r0 + kbA + 4]; al[mt][3] = Hl[r8 + kbA + 4];
            }
            #pragma unroll
            for (int nt = 0; nt < 8; nt++) {
                int nr = (half*64 + nt*8 + g)*CPAD;
                uint32_t bh0 = Wth[nr + kbW], bh1 = Wth[nr + kbW + 4];
                uint32_t bl0 = Wtl[nr + kbW], bl1 = Wtl[nr + kbW + 4];
                #pragma unroll
                for (int mt = 0; mt < 2; mt++) {
                    mma_f16(acc[mt][nt], ah[mt][0], ah[mt][1], ah[mt][2], ah[mt][3], bh0, bh1);
                    mma_f16(acc[mt][nt], ah[mt][0], ah[mt][1], ah[mt][2], ah[mt][3], bl0, bl1);
                    mma_f16(acc[mt][nt], al[mt][0], al[mt][1], al[mt][2], al[mt][3], bh0, bh1);
                }
            }
        }
    }

    bool writer = ((g & 1) == 0);
    #pragma unroll
    for (int mt = 0; mt < 2; mt++)
        #pragma unroll
        for (int nt = 0; nt < 8; nt++) {
            float c0 = acc[mt][nt][0], c1 = acc[mt][nt][1];
            float c2 = acc[mt][nt][2], c3 = acc[mt][nt][3];
            c0 = fmaxf(c0, __shfl_xor_sync(0xffffffffu, c0, 4));
            c1 = fmaxf(c1, __shfl_xor_sync(0xffffffffu, c1, 4));
            c2 = fmaxf(c2, __shfl_xor_sync(0xffffffffu, c2, 4));
            c3 = fmaxf(c3, __shfl_xor_sync(0xffffffffu, c3, 4));
            int col = half*64 + nt*8 + 2*tig;
            float bb0 = b2s[col], bb1 = b2s[col+1];
            if (writer) {
                int p0 = (m0 + band*32 + mt*16 + g) >> 1;
                float o00 = fmaxf(c0 + bb0, 0.f), o01 = fmaxf(c1 + bb1, 0.f);
                float o10 = fmaxf(c2 + bb0, 0.f), o11 = fmaxf(c3 + bb1, 0.f);
                *(float2*)(yout + (size_t)p0*128 + col) = make_float2(o00, o01);
                *(float2*)(yout + (size_t)(p0 + 4)*128 + col) = make_float2(o10, o11);
                uint32_t hw, lw;
                f16_split2(o00, o01, hw, lw);
                yhout[(size_t)p0*64 + (col >> 1)] = hw;
                ylout[(size_t)p0*64 + (col >> 1)] = lw;
                f16_split2(o10, o11, hw, lw);
                yhout[(size_t)(p0 + 4)*64 + (col >> 1)] = hw;
                ylout[(size_t)(p0 + 4)*64 + (col >> 1)] = lw;
            }
        }
}

// ======= conv2/3 (HMMA f16): E'=[yi;yj] (presplit) @ W'(256x128), cp.async
// 8 K-32 chunks, ping-pong. buffer: Eh|El|Wth|Wtl each [128][20] u32.
#define CBS 20
#define CB_BUFU (4*128*CBS)              // 10240 u32 per buffer
#define CB_BIAS 81920
#define CB_IDX  82432
#define CB_SMEM 82944

__global__ void __launch_bounds__(256, 2)
convB_mma_kernel(const uint32_t* __restrict__ yhin, const uint32_t* __restrict__ ylin,
                 const int* __restrict__ idxg,
                 const uint32_t* __restrict__ cwh, const uint32_t* __restrict__ cwl,
                 const float* __restrict__ bias,
                 float* __restrict__ yout,
                 uint32_t* __restrict__ yhout, uint32_t* __restrict__ ylout) {
    extern __shared__ char smem[];
    float* sbias = (float*)(smem + CB_BIAS);
    int*   sidx  = (int*)(smem + CB_IDX);
    uint32_t smb = smem_u32(smem);

    int tid = threadIdx.x, lane = tid & 31, wid = tid >> 5;
    int g = lane >> 2, tig = lane & 3;
    int band = wid & 3, half = wid >> 2;
    int m0 = blockIdx.x*128;
    int bbase = ((m0 >> 1) >> 10) << 10;
    if (tid < 128) { sidx[tid] = idxg[m0 + tid]; sbias[tid] = bias[tid]; }

    auto issueC = [&](int c) {
        int p = c & 1;
        uint32_t base = smb + (uint32_t)(p*40960);
        int kpb = (c & 3)*16;
        bool ipart = c < 4;
        #pragma unroll
        for (int w = 0; w < 8; w++) {
            int v = tid + w*256;
            if (v < 1024) {            // E: 128 rows x 4 q x 2 arrays
                int r = v >> 3, qq = (v >> 1) & 3, a = v & 1;
                int rowg = ipart ? ((m0 + r) >> 1) : (bbase + sidx[r]);
                uint32_t dst = base + (uint32_t)((a*2560 + r*CBS + qq*4)*4);
                const uint32_t* src = (a ? ylin : yhin) + (size_t)rowg*64 + kpb + qq*4;
                cp16(dst, src);
            } else {                   // W: 128 n x 4 q x 2 arrays
                int u = v - 1024;
                int n = u >> 3, qq = (u >> 1) & 3, a = u & 1;
                uint32_t dst = base + (uint32_t)((5120 + a*2560 + n*CBS + qq*4)*4);
                const uint32_t* src = (a ? cwl : cwh) + n*128 + c*16 + qq*4;
                cp16(dst, src);
            }
        }
    };

    issueC(0);
    CP_COMMIT();

    float acc[2][8][4];
    #pragma unroll
    for (int mt = 0; mt < 2; mt++)
        #pragma unroll
        for (int nt = 0; nt < 8; nt++)
            #pragma unroll
            for (int q = 0; q < 4; q++) acc[mt][nt][q] = 0.f;

    for (int c = 0; c < 8; c++) {
        CP_WAIT0();
        __syncthreads();
        if (c + 1 < 8) { issueC(c + 1); CP_COMMIT(); }

        uint32_t* Eh  = (uint32_t*)(smem + (c & 1)*40960);
        uint32_t* El  = Eh + 2560;
        uint32_t* Wth = Eh + 5120;
        uint32_t* Wtl = Eh + 7680;

        #pragma unroll
        for (int ks = 0; ks < 2; ks++) {
            int kb = ks*8 + tig;
            uint32_t ah[2][4], al[2][4];
            #pragma unroll
            for (int mt = 0; mt < 2; mt++) {
                int r0 = (band*32 + mt*16 + g)*CBS;
                int r8 = r0 + 8*CBS;
                ah[mt][0] = Eh[r0 + kb];     ah[mt][1] = Eh[r8 + kb];
                ah[mt][2] = Eh[r0 + kb + 4]; ah[mt][3] = Eh[r8 + kb + 4];
                al[mt][0] = El[r0 + kb];     al[mt][1] = El[r8 + kb];
                al[mt][2] = El[r0 + kb + 4]; al[mt][3] = El[r8 + kb + 4];
            }
            #pragma unroll
            for (int nt = 0; nt < 8; nt++) {
                int nr = (half*64 + nt*8 + g)*CBS;
                uint32_t bh0 = Wth[nr + kb], bh1 = Wth[nr + kb + 4];
                uint32_t bl0 = Wtl[nr + kb], bl1 = Wtl[nr + kb + 4];
                #pragma unroll
                for (int mt = 0; mt < 2; mt++) {
                    mma_f16(acc[mt][nt], ah[mt][0], ah[mt][1], ah[mt][2], ah[mt][3], bh0, bh1);
                    mma_f16(acc[mt][nt], ah[mt][0], ah[mt][1], ah[mt][2], ah[mt][3], bl0, bl1);
                    mma_f16(acc[mt][nt], al[mt][0], al[mt][1], al[mt][2], al[mt][3], bh0, bh1);
                }
            }
        }
    }

    bool writer = ((g & 1) == 0);
    #pragma unroll
    for (int mt = 0; mt < 2; mt++)
        #pragma unroll
        for (int nt = 0; nt < 8; nt++) {
            float c0 = acc[mt][nt][0], c1 = acc[mt][nt][1];
            float c2 = acc[mt][nt][2], c3 = acc[mt][nt][3];
            c0 = fmaxf(c0, __shfl_xor_sync(0xffffffffu, c0, 4));
            c1 = fmaxf(c1, __shfl_xor_sync(0xffffffffu, c1, 4));
            c2 = fmaxf(c2, __shfl_xor_sync(0xffffffffu, c2, 4));
            c3 = fmaxf(c3, __shfl_xor_sync(0xffffffffu, c3, 4));
            int col = half*64 + nt*8 + 2*tig;
            float bb0 = sbias[col], bb1 = sbias[col+1];
            if (writer) {
                int p0 = (m0 + band*32 + mt*16 + g) >> 1;
                float o00 = fmaxf(c0 + bb0, 0.f), o01 = fmaxf(c1 + bb1, 0.f);
                float o10 = fmaxf(c2 + bb0, 0.f), o11 = fmaxf(c3 + bb1, 0.f);
                *(float2*)(yout + (size_t)p0*128 + col) = make_float2(o00, o01);
                *(float2*)(yout + (size_t)(p0 + 4)*128 + col) = make_float2(o10, o11);
                uint32_t hw, lw;
                f16_split2(o00, o01, hw, lw);
                yhout[(size_t)p0*64 + (col >> 1)] = hw;
                ylout[(size_t)p0*64 + (col >> 1)] = lw;
                f16_split2(o10, o11, hw, lw);
                yhout[(size_t)(p0 + 4)*64 + (col >> 1)] = hw;
                ylout[(size_t)(p0 + 4)*64 + (col >> 1)] = lw;
            }
        }
}

// ------------------------------------------------ mean/max pool over nodes
__global__ void __launch_bounds__(128) pool_kernel(const float* __restrict__ y1,
                                                   const float* __restrict__ y2,
                                                   const float* __restrict__ y3,
                                                   float* __restrict__ g) {
    int b = blockIdx.x, s = blockIdx.y, t = threadIdx.x;
    const float* src = (s == 0) ? y1 : ((s == 1) ? y2 : y3);
    const float* p = src + (size_t)b*NN*WW + t;
    float sum = 0.f, mx = -CUDART_INF_F;
    #pragma unroll 4
    for (int n = 0; n < NN; n++) {
        float v = p[(size_t)n*WW];
        sum += v; mx = fmaxf(mx, v);
    }
    int c = s*WW + t;
    g[b*DD2 + c]       = sum * (1.f/1024.f);
    g[b*DD2 + 384 + c] = mx;
}

// --------------------------------- batchnorm (batch stats), 6-block split
__global__ void __launch_bounds__(128) bn_kernel(const float* __restrict__ g,
                                                 const float* __restrict__ gam,
                                                 const float* __restrict__ bet,
                                                 float* __restrict__ h) {
    int c = blockIdx.x*128 + threadIdx.x;
    float mu = 0.f;
    for (int b = 0; b < BB; b++) mu += g[b*DD2 + c];
    mu *= (1.f/64.f);
    float var = 0.f;
    for (int b = 0; b < BB; b++) { float d = g[b*DD2 + c] - mu; var += d*d; }
    var *= (1.f/64.f);
    float sc = rsqrtf(var + 1e-5f) * gam[c];
    float be = bet[c];
    for (int b = 0; b < BB; b++)
        h[b*DD2 + c] = (g[b*DD2 + c] - mu)*sc + be;
}

// --------------------------------------------- 768x768 linear + leaky relu
__global__ void __launch_bounds__(128) linear_kernel(const float* __restrict__ hin,
                                                     const float* __restrict__ Wt,
                                                     const float* __restrict__ bias,
                                                     float* __restrict__ hout) {
    __shared__ float sh[DD2];
    int b = blockIdx.x;
    for (int v = threadIdx.x; v < DD2; v += 128) sh[v] = hin[b*DD2 + v];
    __syncthreads();
    int o = blockIdx.y*128 + threadIdx.x;
    float acc = bias[o];
    #pragma unroll 8
    for (int k = 0; k < DD2; k++) acc += sh[k]*Wt[(size_t)k*DD2 + o];
    acc = (acc >= 0.f) ? acc : 0.01f*acc;
    hout[b*DD2 + o] = acc;
}

// ------------------------------------------------------------ output layer
__global__ void __launch_bounds__(256) out_kernel(const float* __restrict__ h,
                                                  const float* __restrict__ ow,
                                                  const float* __restrict__ ob,
                                                  float* __restrict__ out) {
    __shared__ float red[256];
    int b = blockIdx.x;
    float acc = 0.f;
    for (int k = threadIdx.x; k < DD2; k += 256) acc += h[b*DD2 + k]*ow[k];
    red[threadIdx.x] = acc;
    __syncthreads();
    for (int s = 128; s; s >>= 1) {
        if (threadIdx.x < s) red[threadIdx.x] += red[threadIdx.x + s];
        __syncthreads();
    }
    if (threadIdx.x == 0) out[b] = red[0] + ob[0];
}

// --------------------------------------------------------------------- host
extern "C" void kernel_launch(void* const* d_in, const int* in_sizes, int n_in,
                              void* d_out, int out_size) {
    (void)in_sizes; (void)n_in; (void)out_size;
    const float* x     = (const float*)d_in[0];
    const float* p1_w1 = (const float*)d_in[1];
    const float* p1_b1 = (const float*)d_in[2];
    const float* p1_w2 = (const float*)d_in[3];
    const float* p1_b2 = (const float*)d_in[4];
    const float* c_w   = (const float*)d_in[5];
    const float* c_b   = (const float*)d_in[6];
    const float* bng   = (const float*)d_in[7];
    const float* bnb   = (const float*)d_in[8];
    const float* lin_w = (const float*)d_in[9];
    const float* lin_b = (const float*)d_in[10];
    const float* out_w = (const float*)d_in[11];
    const float* out_b = (const float*)d_in[12];
    float* out = (float*)d_out;

    float *y1, *y2, *y3, *sq, *gg, *hA, *hB; int* idx;
    uint32_t *yh, *yl, *cwh, *cwl;
    cudaGetSymbolAddress((void**)&y1, d_y1);
    cudaGetSymbolAddress((void**)&y2, d_y2);
    cudaGetSymbolAddress((void**)&y3, d_y3);
    cudaGetSymbolAddress((void**)&yh, d_yh);
    cudaGetSymbolAddress((void**)&yl, d_yl);
    cudaGetSymbolAddress((void**)&sq, d_sq);
    cudaGetSymbolAddress((void**)&gg, d_g);
    cudaGetSymbolAddress((void**)&hA, d_hA);
    cudaGetSymbolAddress((void**)&hB, d_hB);
    cudaGetSymbolAddress((void**)&idx, d_idx);
    cudaGetSymbolAddress((void**)&cwh, d_cwh);
    cudaGetSymbolAddress((void**)&cwl, d_cwl);

    const size_t YSP = (size_t)BB*NN*64;   // per-buffer size of yh/yl

    cudaFuncSetAttribute((const void*)knn128_mma_kernel,
                         cudaFuncAttributeMaxDynamicSharedMemorySize, KNNMMA_SMEM);
    cudaFuncSetAttribute((const void*)convAF_mma_kernel,
                         cudaFuncAttributeMaxDynamicSharedMemorySize, AF_SMEM);
    cudaFuncSetAttribute((const void*)convB_mma_kernel,
                         cudaFuncAttributeMaxDynamicSharedMemorySize, CB_SMEM);

    prep_conv_kernel<<<(128*64 + 2*128*128)/256, 256>>>(p1_w2, c_w);

    knn5_kernel  <<<dim3(4, BB), 256>>>(x, idx);
    convAF_mma_kernel<<<MTOT/128, 256, AF_SMEM>>>(x, idx, p1_w1, p1_b1, p1_b2,
                                                  y1, yh, yl);

    sqnorm_kernel<<<(BB*NN)/8, 256>>>(y1, sq);
    knn128_mma_kernel<<<dim3(NN/128, BB), 256, KNNMMA_SMEM>>>(yh, yl, y1, sq, idx);
    convB_mma_kernel<<<MTOT/128, 256, CB_SMEM>>>(yh, yl, idx, cwh, cwl, c_b,
                                                 y2, yh + YSP, yl + YSP);

    sqnorm_kernel<<<(BB*NN)/8, 256>>>(y2, sq);
    knn128_mma_kernel<<<dim3(NN/128, BB), 256, KNNMMA_SMEM>>>(yh + YSP, yl + YSP,
                                                              y2, sq, idx);
    convB_mma_kernel<<<MTOT/128, 256, CB_SMEM>>>(yh + YSP, yl + YSP, idx,
                                                 cwh + 16384, cwl + 16384,
                                                 c_b + 128, y3, yh, yl);

    pool_kernel<<<dim3(BB, 3), 128>>>(y1, y2, y3, gg);
    bn_kernel  <<<6, 128>>>(gg, bng, bnb, hA);

    const float* lin_in = hA; float* lin_out = hB;
    for (int l = 0; l < 5; l++) {
        linear_kernel<<<dim3(BB, DD2/128), 128>>>(lin_in,
                                                  lin_w + (size_t)l*DD2*DD2,
                                                  lin_b + l*DD2, lin_out);
        const float* t = lin_in; lin_in = lin_out; lin_out = (float*)t;
    }
    out_kernel<<<BB, 256>>>(lin_in, out_w, out_b, out);
}